// round 2
// baseline (speedup 1.0000x reference)
#include <cuda_runtime.h>

#define BATCH 4
#define SEQ   2048
#define DIMS  1024
#define NHEAD 16
#define HDIM  64
#define MROWS (BATCH*SEQ)

typedef unsigned long long ull;

// Packed dual-fp32 ops (sm_103a FFMA2 path — PTX only, ptxas won't auto-fuse)
#define FMA2(d,a,b,c) asm("fma.rn.f32x2 %0,%1,%2,%3;" : "=l"(d) : "l"(a), "l"(b), "l"(c))
#define MUL2(d,a,b)   asm("mul.rn.f32x2 %0,%1,%2;"    : "=l"(d) : "l"(a), "l"(b))
#define PACK2(o,x)    asm("mov.b64 %0,{%1,%1};" : "=l"(o) : "r"(__float_as_uint(x)))
#define UNPK2(lo,hi,in) asm("mov.b64 {%0,%1},%2;" : "=f"(lo), "=f"(hi) : "l"(in))

// Fast 2^t: round-to-int bit trick + deg-4 Taylor on [-0.5,0.5]. err ~4e-5.
__device__ __forceinline__ float exp2_fast(float t) {
    t = fmaxf(t, -126.0f);
    float r = t + 12582912.0f;            // 1.5*2^23: rounds t into mantissa
    int   i = __float_as_int(r) << 23;    // == n<<23 exactly (low bits of C are 0)
    float f = t - (r - 12582912.0f);
    float p = fmaf(f, 0.00961813f, 0.05550411f);
    p = fmaf(f, p, 0.24022651f);
    p = fmaf(f, p, 0.69314718f);
    p = fmaf(f, p, 1.0f);
    return __int_as_float(__float_as_int(p) + i);
}

// Scratch
__device__ float g_q[(size_t)BATCH*NHEAD*SEQ*HDIM];   // [b,h,s,d] (pre-scaled by 0.125*log2e)
__device__ float g_k[(size_t)BATCH*NHEAD*SEQ*HDIM];
__device__ float g_v[(size_t)BATCH*NHEAD*SEQ*HDIM];
__device__ float g_ctx[(size_t)BATCH*SEQ*DIMS];       // [b,s,h*64+d]

// ---------------------------------------------------------------------------
// Projection GEMM with packed f32x2 inner product.
// C = scale*(A[M,K] @ W[N,K]^T + bias). 128x128x16 tile, 256 thr, 8x8/thread.
// ---------------------------------------------------------------------------
template<int OUT_SEL, int A_SEL>
__global__ __launch_bounds__(256, 2) void proj_kernel(
    const float* __restrict__ Ap, const float* __restrict__ W,
    const float* __restrict__ bias, float* __restrict__ outp, float scale)
{
    const float* __restrict__ A = (A_SEL == 1) ? (const float*)g_ctx : Ap;
    float* out;
    if      (OUT_SEL == 0) out = g_q;
    else if (OUT_SEL == 1) out = g_k;
    else if (OUT_SEL == 2) out = g_v;
    else                   out = outp;

    const int BK = 16, LDT = 132;
    __shared__ float As[16*132];
    __shared__ float Bs[16*132];

    const int tid = threadIdx.x;
    const int m0 = blockIdx.y * 128;
    const int n0 = blockIdx.x * 128;
    const int tx = tid & 15;
    const int ty = tid >> 4;
    const int lr = tid >> 2;
    const int lc = (tid & 3) << 2;

    ull acc2[8][4];
#pragma unroll
    for (int i = 0; i < 8; ++i)
#pragma unroll
        for (int j = 0; j < 4; ++j) acc2[i][j] = 0ull;

    for (int k0 = 0; k0 < DIMS; k0 += BK) {
#pragma unroll
        for (int rr = 0; rr < 2; ++rr) {
            const int row = lr + rr * 64;
            float4 av = *(const float4*)&A[(size_t)(m0 + row) * DIMS + k0 + lc];
            As[(lc+0)*LDT + row] = av.x;
            As[(lc+1)*LDT + row] = av.y;
            As[(lc+2)*LDT + row] = av.z;
            As[(lc+3)*LDT + row] = av.w;
            float4 wv4 = *(const float4*)&W[(size_t)(n0 + row) * DIMS + k0 + lc];
            Bs[(lc+0)*LDT + row] = wv4.x;
            Bs[(lc+1)*LDT + row] = wv4.y;
            Bs[(lc+2)*LDT + row] = wv4.z;
            Bs[(lc+3)*LDT + row] = wv4.w;
        }
        __syncthreads();
#pragma unroll
        for (int kk = 0; kk < BK; ++kk) {
            float4 a0 = *(const float4*)&As[kk*LDT + ty*8];
            float4 a1 = *(const float4*)&As[kk*LDT + ty*8 + 4];
            ull b2[4];
#pragma unroll
            for (int j = 0; j < 4; ++j)
                b2[j] = *(const ull*)&Bs[kk*LDT + tx*8 + 2*j];
            float av[8] = {a0.x,a0.y,a0.z,a0.w,a1.x,a1.y,a1.z,a1.w};
#pragma unroll
            for (int i = 0; i < 8; ++i) {
                ull aa; PACK2(aa, av[i]);
#pragma unroll
                for (int j = 0; j < 4; ++j)
                    FMA2(acc2[i][j], aa, b2[j], acc2[i][j]);
            }
        }
        __syncthreads();
    }

#pragma unroll
    for (int i = 0; i < 8; ++i) {
        const int m = m0 + ty*8 + i;
        float c[8];
#pragma unroll
        for (int j = 0; j < 4; ++j) UNPK2(c[2*j], c[2*j+1], acc2[i][j]);
#pragma unroll
        for (int jj = 0; jj < 2; ++jj) {
            const int n = n0 + tx*8 + jj*4;
            float4 bb = *(const float4*)&bias[n];
            float4 r;
            r.x = (c[jj*4+0] + bb.x) * scale;
            r.y = (c[jj*4+1] + bb.y) * scale;
            r.z = (c[jj*4+2] + bb.z) * scale;
            r.w = (c[jj*4+3] + bb.w) * scale;
            if (OUT_SEL < 3) {
                const int bb_ = m / SEQ, s = m % SEQ;
                const int h = n / HDIM, d = n % HDIM;
                *(float4*)&out[(((size_t)bb_*NHEAD + h)*SEQ + s)*HDIM + d] = r;
            } else {
                *(float4*)&out[(size_t)m*DIMS + n] = r;
            }
        }
    }
}

// ---------------------------------------------------------------------------
// Flash attention, fp32 with packed FFMA2 + polynomial exp2.
// 128q x 128k tile per CTA, 256 threads (16x16), 8x8 per thread in S,
// 8q x 4d per thread in the output accumulator.
// Q pre-scaled by 0.125*log2e, so softmax = 2^(t - max t).
// ---------------------------------------------------------------------------
#define LDQ 132
#define LDK 132
#define LDV 68
#define LDP 132
#define ATTN_SMEM_FLOATS (64*LDQ + 64*LDK + 128*LDV + 128*LDP + 128)
#define ATTN_SMEM_BYTES  (ATTN_SMEM_FLOATS * 4)

__global__ __launch_bounds__(256) void attn_kernel(const int* __restrict__ mask)
{
    extern __shared__ float sm[];
    float* Qs = sm;                 // [64 d][LDQ] (transposed)
    float* Ks = Qs + 64*LDQ;        // [64 d][LDK] (transposed)
    float* Vs = Ks + 64*LDK;        // [128 k][LDV] (natural)
    float* Ps = Vs + 128*LDV;       // [128 q][LDP] (natural)
    int*   Ms = (int*)(Ps + 128*LDP);

    const int bh = blockIdx.y;
    const int b  = bh >> 4;
    const int h  = bh & 15;
    const int q0 = blockIdx.x * 128;
    const float* __restrict__ Qg = g_q + (size_t)bh*SEQ*HDIM;
    const float* __restrict__ Kg = g_k + (size_t)bh*SEQ*HDIM;
    const float* __restrict__ Vg = g_v + (size_t)bh*SEQ*HDIM;

    const int tid = threadIdx.x;
    const int tx = tid & 15;   // k-col group (8 wide) / d group (4 wide)
    const int ty = tid >> 4;   // q-row group (8 wide)

    // Load Q tile once, transposed [d][q]
#pragma unroll
    for (int it = 0; it < 8; ++it) {
        int idx = tid + it*256;          // 0..2047
        int r = idx & 127, c4 = (idx >> 7) << 2;
        float4 v = *(const float4*)&Qg[(size_t)(q0 + r)*HDIM + c4];
        Qs[(c4+0)*LDQ + r] = v.x;
        Qs[(c4+1)*LDQ + r] = v.y;
        Qs[(c4+2)*LDQ + r] = v.z;
        Qs[(c4+3)*LDQ + r] = v.w;
    }

    ull acc2[8][2];
    float m_i[8], l_i[8];
#pragma unroll
    for (int i = 0; i < 8; ++i) {
        m_i[i] = -1e30f; l_i[i] = 0.f;
        acc2[i][0] = 0ull; acc2[i][1] = 0ull;
    }

    for (int k0 = 0; k0 < SEQ; k0 += 128) {
        __syncthreads();  // prior PV done with Ps/Vs, prior QK done with Ks
#pragma unroll
        for (int it = 0; it < 8; ++it) {
            int idx = tid + it*256;
            int r = idx & 127, c4 = (idx >> 7) << 2;
            float4 kv = *(const float4*)&Kg[(size_t)(k0 + r)*HDIM + c4];
            Ks[(c4+0)*LDK + r] = kv.x;
            Ks[(c4+1)*LDK + r] = kv.y;
            Ks[(c4+2)*LDK + r] = kv.z;
            Ks[(c4+3)*LDK + r] = kv.w;
            *(float4*)&Vs[r*LDV + c4] = *(const float4*)&Vg[(size_t)(k0 + r)*HDIM + c4];
        }
        if (tid < 128) Ms[tid] = mask[b*SEQ + k0 + tid];
        __syncthreads();

        // ---- S = Q K^T (8x8 per thread, packed) ----
        ull s2[8][4];
#pragma unroll
        for (int i = 0; i < 8; ++i)
#pragma unroll
            for (int j = 0; j < 4; ++j) s2[i][j] = 0ull;

#pragma unroll 8
        for (int kk = 0; kk < HDIM; ++kk) {
            float4 qa = *(const float4*)&Qs[kk*LDQ + ty*8];
            float4 qb = *(const float4*)&Qs[kk*LDQ + ty*8 + 4];
            ull k2[4];
#pragma unroll
            for (int j = 0; j < 4; ++j)
                k2[j] = *(const ull*)&Ks[kk*LDK + tx*8 + 2*j];
            float qv[8] = {qa.x,qa.y,qa.z,qa.w,qb.x,qb.y,qb.z,qb.w};
#pragma unroll
            for (int i = 0; i < 8; ++i) {
                ull qq; PACK2(qq, qv[i]);
#pragma unroll
                for (int j = 0; j < 4; ++j)
                    FMA2(s2[i][j], qq, k2[j], s2[i][j]);
            }
        }

        // unpack + mask
        float sf[8][8];
#pragma unroll
        for (int i = 0; i < 8; ++i)
#pragma unroll
            for (int j = 0; j < 4; ++j)
                UNPK2(sf[i][2*j], sf[i][2*j+1], s2[i][j]);
#pragma unroll
        for (int j = 0; j < 8; ++j) {
            if (Ms[tx*8 + j] == 0) {
#pragma unroll
                for (int i = 0; i < 8; ++i) sf[i][j] = -1e30f;
            }
        }

        // ---- online softmax (base-2), rows span 16 tx lanes ----
#pragma unroll
        for (int i = 0; i < 8; ++i) {
            float rm = sf[i][0];
#pragma unroll
            for (int j = 1; j < 8; ++j) rm = fmaxf(rm, sf[i][j]);
#pragma unroll
            for (int off = 1; off < 16; off <<= 1)
                rm = fmaxf(rm, __shfl_xor_sync(0xffffffffu, rm, off));
            const float mn = fmaxf(m_i[i], rm);
            const float corr = exp2_fast(m_i[i] - mn);
            m_i[i] = mn;
            float rs = 0.f;
#pragma unroll
            for (int j = 0; j < 8; ++j) {
                sf[i][j] = exp2_fast(sf[i][j] - mn);
                rs += sf[i][j];
            }
#pragma unroll
            for (int off = 1; off < 16; off <<= 1)
                rs += __shfl_xor_sync(0xffffffffu, rs, off);
            l_i[i] = l_i[i]*corr + rs;
            ull cc; PACK2(cc, corr);
            MUL2(acc2[i][0], acc2[i][0], cc);
            MUL2(acc2[i][1], acc2[i][1], cc);
            *(float4*)&Ps[(ty*8+i)*LDP + tx*8]     = make_float4(sf[i][0], sf[i][1], sf[i][2], sf[i][3]);
            *(float4*)&Ps[(ty*8+i)*LDP + tx*8 + 4] = make_float4(sf[i][4], sf[i][5], sf[i][6], sf[i][7]);
        }
        __syncthreads();

        // ---- acc += P @ V  (P as float4 along k; V pairs along d) ----
#pragma unroll 2
        for (int kk = 0; kk < 128; kk += 4) {
            float4 p[8];
#pragma unroll
            for (int i = 0; i < 8; ++i)
                p[i] = *(const float4*)&Ps[(ty*8+i)*LDP + kk];
            ull v2[4][2];
#pragma unroll
            for (int u = 0; u < 4; ++u) {
                v2[u][0] = *(const ull*)&Vs[(kk+u)*LDV + tx*4];
                v2[u][1] = *(const ull*)&Vs[(kk+u)*LDV + tx*4 + 2];
            }
#pragma unroll
            for (int u = 0; u < 4; ++u) {
#pragma unroll
                for (int i = 0; i < 8; ++i) {
                    float pv = (u == 0) ? p[i].x : (u == 1) ? p[i].y : (u == 2) ? p[i].z : p[i].w;
                    ull pp; PACK2(pp, pv);
                    FMA2(acc2[i][0], pp, v2[u][0], acc2[i][0]);
                    FMA2(acc2[i][1], pp, v2[u][1], acc2[i][1]);
                }
            }
        }
    }

    // normalize + write ctx [b,s,h*64+d]
#pragma unroll
    for (int i = 0; i < 8; ++i) {
        const int srow = q0 + ty*8 + i;
        const float inv = 1.f / l_i[i];
        float c0, c1, c2, c3;
        UNPK2(c0, c1, acc2[i][0]);
        UNPK2(c2, c3, acc2[i][1]);
        float4 r = make_float4(c0*inv, c1*inv, c2*inv, c3*inv);
        *(float4*)&g_ctx[((size_t)b*SEQ + srow)*DIMS + h*HDIM + tx*4] = r;
    }
}

// ---------------------------------------------------------------------------
extern "C" void kernel_launch(void* const* d_in, const int* in_sizes, int n_in,
                              void* d_out, int out_size)
{
    const float* input = (const float*)d_in[0];
    const int*   mask  = (const int*)d_in[1];
    const float* wq = (const float*)d_in[2];
    const float* bq = (const float*)d_in[3];
    const float* wk = (const float*)d_in[4];
    const float* bk = (const float*)d_in[5];
    const float* wv = (const float*)d_in[6];
    const float* bv = (const float*)d_in[7];
    const float* wo = (const float*)d_in[8];
    const float* bo = (const float*)d_in[9];
    float* out = (float*)d_out;

    (void)in_sizes; (void)n_in; (void)out_size;

    dim3 pgrid(DIMS/128, MROWS/128);   // 8 x 64

    // Q scaled by (1/sqrt(64)) * log2(e) so softmax runs in base 2
    proj_kernel<0,0><<<pgrid, 256>>>(input, wq, bq, nullptr, 0.125f * 1.44269504f);
    proj_kernel<1,0><<<pgrid, 256>>>(input, wk, bk, nullptr, 1.0f);
    proj_kernel<2,0><<<pgrid, 256>>>(input, wv, bv, nullptr, 1.0f);

    cudaFuncSetAttribute(attn_kernel,
                         cudaFuncAttributeMaxDynamicSharedMemorySize,
                         ATTN_SMEM_BYTES);
    attn_kernel<<<dim3(SEQ/128, BATCH*NHEAD), 256, ATTN_SMEM_BYTES>>>(mask);

    proj_kernel<3,1><<<pgrid, 256>>>(nullptr, wo, bo, out, 1.0f);
}

// round 4
// speedup vs baseline: 1.1879x; 1.1879x over previous
#include <cuda_runtime.h>
#include <cuda_bf16.h>
#include <cstdint>

#define BATCH 4
#define SEQ   2048
#define DIMS  1024
#define NHEAD 16
#define HDIM  64
#define MROWS (BATCH*SEQ)

typedef unsigned int u32;
typedef unsigned long long u64;

// ---------------- scratch (static device allocations) ----------------
__device__ __nv_bfloat16 g_ah[(size_t)MROWS*DIMS];     // A hi (X, later ctx)
__device__ __nv_bfloat16 g_al[(size_t)MROWS*DIMS];     // A lo
__device__ __nv_bfloat16 g_wh[4ull*DIMS*DIMS];         // wq,wk,wv,wo hi
__device__ __nv_bfloat16 g_wl[4ull*DIMS*DIMS];         // lo
__device__ float g_q[(size_t)MROWS*DIMS];              // [b*S+s, h*64+d]
__device__ float g_k[(size_t)MROWS*DIMS];
__device__ float g_v[(size_t)MROWS*DIMS];
__device__ float g_ctx[(size_t)MROWS*DIMS];

// ---------------- helpers ----------------
__device__ __forceinline__ u32 smem_u32(const void* p) {
    u32 a;
    asm("{ .reg .u64 t; cvta.to.shared.u64 t, %1; cvt.u32.u64 %0, t; }" : "=r"(a) : "l"(p));
    return a;
}
#define CP_ASYNC16(d, g) \
    asm volatile("cp.async.cg.shared.global [%0], [%1], 16;" :: "r"(d), "l"(g) : "memory")
#define CP_COMMIT() asm volatile("cp.async.commit_group;" ::: "memory")
#define CP_WAIT1()  asm volatile("cp.async.wait_group 1;" ::: "memory")
#define CP_WAIT0()  asm volatile("cp.async.wait_group 0;" ::: "memory")

#define LDSM4(r0, r1, r2, r3, a) \
    asm volatile("ldmatrix.sync.aligned.m8n8.x4.shared.b16 {%0,%1,%2,%3}, [%4];" \
                 : "=r"(r0), "=r"(r1), "=r"(r2), "=r"(r3) : "r"(a))

#define MMA_BF16(d, a, b0, b1) \
    asm volatile("mma.sync.aligned.m16n8k16.row.col.f32.bf16.bf16.f32 " \
                 "{%0,%1,%2,%3}, {%4,%5,%6,%7}, {%8,%9}, {%0,%1,%2,%3};" \
                 : "+f"((d)[0]), "+f"((d)[1]), "+f"((d)[2]), "+f"((d)[3]) \
                 : "r"((a)[0]), "r"((a)[1]), "r"((a)[2]), "r"((a)[3]), \
                   "r"(b0), "r"(b1))

// Fast 2^t
__device__ __forceinline__ float exp2_fast(float t) {
    t = fmaxf(t, -126.0f);
    float r = t + 12582912.0f;
    int   i = __float_as_int(r) << 23;
    float f = t - (r - 12582912.0f);
    float p = fmaf(f, 0.00961813f, 0.05550411f);
    p = fmaf(f, p, 0.24022651f);
    p = fmaf(f, p, 0.69314718f);
    p = fmaf(f, p, 1.0f);
    return __int_as_float(__float_as_int(p) + i);
}

// ---------------- fp32 -> bf16 hi/lo split ----------------
__global__ void cvt_kernel(const float* __restrict__ srcp, int src_sel,
                           int dst_sel, size_t dst_off, int n4)
{
    const float* __restrict__ src = (src_sel == 1) ? (const float*)g_ctx : srcp;
    __nv_bfloat16* H = (dst_sel == 0 ? g_ah : g_wh) + dst_off;
    __nv_bfloat16* L = (dst_sel == 0 ? g_al : g_wl) + dst_off;
    int i = blockIdx.x * 256 + threadIdx.x;
    if (i >= n4) return;
    float4 v = ((const float4*)src)[i];
    __nv_bfloat16 h0 = __float2bfloat16_rn(v.x);
    __nv_bfloat16 h1 = __float2bfloat16_rn(v.y);
    __nv_bfloat16 h2 = __float2bfloat16_rn(v.z);
    __nv_bfloat16 h3 = __float2bfloat16_rn(v.w);
    __nv_bfloat16 l0 = __float2bfloat16_rn(v.x - __bfloat162float(h0));
    __nv_bfloat16 l1 = __float2bfloat16_rn(v.y - __bfloat162float(h1));
    __nv_bfloat16 l2 = __float2bfloat16_rn(v.z - __bfloat162float(h2));
    __nv_bfloat16 l3 = __float2bfloat16_rn(v.w - __bfloat162float(h3));
    u32 ph0 = ((u32)__bfloat16_as_ushort(h1) << 16) | __bfloat16_as_ushort(h0);
    u32 ph1 = ((u32)__bfloat16_as_ushort(h3) << 16) | __bfloat16_as_ushort(h2);
    u32 pl0 = ((u32)__bfloat16_as_ushort(l1) << 16) | __bfloat16_as_ushort(l0);
    u32 pl1 = ((u32)__bfloat16_as_ushort(l3) << 16) | __bfloat16_as_ushort(l2);
    ((u32*)H)[i*2+0] = ph0;
    ((u32*)H)[i*2+1] = ph1;
    ((u32*)L)[i*2+0] = pl0;
    ((u32*)L)[i*2+1] = pl1;
}

// ---------------- mma.sync split-bf16 GEMM ----------------
// C[m0:+128, n0:+128] = scale*(A @ W^T + bias), via Ah*Bh + Ah*Bl + Al*Bh.
// 256 threads, warp grid 2(m)x4(n), warp tile 64x32, BK=32, 2-stage cp.async.
#define GSTR   40                      // smem row stride in halves (32 + 8 pad)
#define MATB   (128*GSTR*2)            // bytes per matrix tile = 10240
#define STAGEB (4*MATB)                // Ah,Al,Bh,Bl
#define GEMM_DSMEM (2*STAGEB)          // 81920

template<int OUT_SEL>
__global__ __launch_bounds__(256) void gemm_kernel(
    int widx, const float* __restrict__ bias, float* __restrict__ outp, float scale)
{
    extern __shared__ __align__(16) char dyn[];
    __shared__ float s_bias[128];

    const int tid = threadIdx.x, wid = tid >> 5, lane = tid & 31;
    const int m0 = blockIdx.y * 128, n0 = blockIdx.x * 128;
    const int wm = (wid >> 2) * 64, wn = (wid & 3) * 32;
    const u32 sbase = smem_u32(dyn);

    if (tid < 128) s_bias[tid] = bias[n0 + tid];

    const __nv_bfloat16* __restrict__ Wh = g_wh + (size_t)widx * DIMS * DIMS;
    const __nv_bfloat16* __restrict__ Wl = g_wl + (size_t)widx * DIMS * DIMS;

    // loader: 64 threads per matrix tile (0=Ah 1=Al 2=Bh 3=Bl)
    const int lmat = tid >> 6;
    const int lt   = tid & 63;
    const __nv_bfloat16* lsrc =
        (lmat == 0) ? (g_ah + (size_t)m0 * DIMS) :
        (lmat == 1) ? (g_al + (size_t)m0 * DIMS) :
        (lmat == 2) ? (Wh   + (size_t)n0 * DIMS) :
                      (Wl   + (size_t)n0 * DIMS);

    auto load_stage = [&](int s, int k0) {
        u32 mb = sbase + s * STAGEB + lmat * MATB;
#pragma unroll
        for (int c = 0; c < 8; ++c) {
            int row = lt * 2 + (c >> 2);
            int cc = c & 3;
            u64 g = (u64)__cvta_generic_to_global(lsrc + (size_t)row * DIMS + k0 + cc * 8);
            CP_ASYNC16(mb + row * (GSTR*2) + cc * 16, g);
        }
        CP_COMMIT();
    };

    float acc[4][4][4];
#pragma unroll
    for (int i = 0; i < 4; ++i)
#pragma unroll
        for (int j = 0; j < 4; ++j)
#pragma unroll
            for (int r = 0; r < 4; ++r) acc[i][j][r] = 0.f;

    const int NIT = DIMS / 32;
    load_stage(0, 0);

    // ldmatrix per-lane row/col offsets (shared by A and B tiles)
    const int lrow = lane & 15;
    const int lkof = ((lane >> 4) & 1) * 8;   // halves

    for (int it = 0; it < NIT; ++it) {
        if (it + 1 < NIT) { load_stage((it + 1) & 1, (it + 1) * 32); CP_WAIT1(); }
        else              { CP_WAIT0(); }
        __syncthreads();

        const u32 st  = sbase + (it & 1) * STAGEB;
        const u32 pAh = st, pAl = st + MATB, pBh = st + 2*MATB, pBl = st + 3*MATB;

#pragma unroll
        for (int ks = 0; ks < 2; ++ks) {
            const int kh = ks * 16 + lkof;            // half offset in row
            u32 ah[4][4], al[4][4], bh[2][4], bl[2][4];
#pragma unroll
            for (int ti = 0; ti < 4; ++ti) {
                u32 ra = (u32)((wm + ti*16 + lrow) * (GSTR*2) + kh*2);
                LDSM4(ah[ti][0], ah[ti][1], ah[ti][2], ah[ti][3], pAh + ra);
                LDSM4(al[ti][0], al[ti][1], al[ti][2], al[ti][3], pAl + ra);
            }
#pragma unroll
            for (int g = 0; g < 2; ++g) {
                u32 rb = (u32)((wn + g*16 + lrow) * (GSTR*2) + kh*2);
                LDSM4(bh[g][0], bh[g][1], bh[g][2], bh[g][3], pBh + rb);
                LDSM4(bl[g][0], bl[g][1], bl[g][2], bl[g][3], pBl + rb);
            }
#pragma unroll
            for (int ti = 0; ti < 4; ++ti) {
#pragma unroll
                for (int nj = 0; nj < 4; ++nj) {
                    const int g = nj >> 1, o = nj & 1;
                    MMA_BF16(acc[ti][nj], ah[ti], bh[g][o],   bh[g][o+2]);
                    MMA_BF16(acc[ti][nj], ah[ti], bl[g][o],   bl[g][o+2]);
                    MMA_BF16(acc[ti][nj], al[ti], bh[g][o],   bh[g][o+2]);
                }
            }
        }
        __syncthreads();
    }

    float* out;
    if      (OUT_SEL == 0) out = g_q;
    else if (OUT_SEL == 1) out = g_k;
    else if (OUT_SEL == 2) out = g_v;
    else                   out = outp;

#pragma unroll
    for (int ti = 0; ti < 4; ++ti) {
#pragma unroll
        for (int nj = 0; nj < 4; ++nj) {
            const int col = wn + nj*8 + (lane & 3)*2;
            const int r0  = m0 + wm + ti*16 + (lane >> 2);
            const float b0 = s_bias[col], b1 = s_bias[col + 1];
            float2 v0 = make_float2((acc[ti][nj][0] + b0) * scale,
                                    (acc[ti][nj][1] + b1) * scale);
            float2 v1 = make_float2((acc[ti][nj][2] + b0) * scale,
                                    (acc[ti][nj][3] + b1) * scale);
            *(float2*)&out[(size_t)r0 * DIMS + n0 + col]       = v0;
            *(float2*)&out[(size_t)(r0+8) * DIMS + n0 + col]   = v1;
        }
    }
}

// ---------------- fp32 flash attention (base-2 softmax) ----------------
#define ATTN_LK 65
#define ATTN_LV 68
#define ATTN_LP 68
#define ATTN_SMEM_FLOATS (HDIM*64 + 64*ATTN_LK + 64*ATTN_LV + 64*ATTN_LP + 64)
#define ATTN_SMEM_BYTES  (ATTN_SMEM_FLOATS * 4)

__global__ __launch_bounds__(256) void attn_kernel(const int* __restrict__ mask)
{
    extern __shared__ float smbuf[];
    float* Qs = smbuf;                    // [64 d][64 row]
    float* Ks = Qs + HDIM*64;             // [64 s][65]
    float* Vs = Ks + 64*ATTN_LK;          // [64 s][68]
    float* Ps = Vs + 64*ATTN_LV;          // [64 row][68]
    int*   Ms = (int*)(Ps + 64*ATTN_LP);

    const int bh = blockIdx.y;
    const int b  = bh >> 4;
    const int h  = bh & 15;
    const int q0 = blockIdx.x * 64;
    const float* __restrict__ Qg = g_q + (size_t)b*SEQ*DIMS + h*HDIM;
    const float* __restrict__ Kg = g_k + (size_t)b*SEQ*DIMS + h*HDIM;
    const float* __restrict__ Vg = g_v + (size_t)b*SEQ*DIMS + h*HDIM;

    const int tid = threadIdx.x;
    const int tx = tid & 15;
    const int ty = tid >> 4;

#pragma unroll
    for (int it = 0; it < 16; ++it) {
        int idx = tid + it*256;
        int r = idx >> 6, d = idx & 63;
        Qs[d*64 + r] = Qg[(size_t)(q0 + r)*DIMS + d];
    }

    float m_i[4], l_i[4], acc[4][4];
#pragma unroll
    for (int i = 0; i < 4; ++i) {
        m_i[i] = -1e30f; l_i[i] = 0.f;
#pragma unroll
        for (int j = 0; j < 4; ++j) acc[i][j] = 0.f;
    }

    for (int k0 = 0; k0 < SEQ; k0 += 64) {
        __syncthreads();
#pragma unroll
        for (int it = 0; it < 4; ++it) {
            int idx = tid + it*256;
            int r = idx >> 4, c = (idx & 15) << 2;
            float4 kv = *(const float4*)&Kg[(size_t)(k0 + r)*DIMS + c];
            Ks[r*ATTN_LK + c + 0] = kv.x;
            Ks[r*ATTN_LK + c + 1] = kv.y;
            Ks[r*ATTN_LK + c + 2] = kv.z;
            Ks[r*ATTN_LK + c + 3] = kv.w;
            *(float4*)&Vs[r*ATTN_LV + c] = *(const float4*)&Vg[(size_t)(k0 + r)*DIMS + c];
        }
        if (tid < 64) Ms[tid] = mask[b*SEQ + k0 + tid];
        __syncthreads();

        float sf[4][4];
#pragma unroll
        for (int i = 0; i < 4; ++i)
#pragma unroll
            for (int j = 0; j < 4; ++j) sf[i][j] = 0.f;

#pragma unroll 8
        for (int kk = 0; kk < HDIM; ++kk) {
            float4 q = *(const float4*)&Qs[kk*64 + ty*4];
            float qa[4] = {q.x, q.y, q.z, q.w};
            float ka[4];
#pragma unroll
            for (int j = 0; j < 4; ++j)
                ka[j] = Ks[(tx*4 + j)*ATTN_LK + kk];
#pragma unroll
            for (int i = 0; i < 4; ++i)
#pragma unroll
                for (int j = 0; j < 4; ++j)
                    sf[i][j] = fmaf(qa[i], ka[j], sf[i][j]);
        }

#pragma unroll
        for (int j = 0; j < 4; ++j) {
            if (Ms[tx*4 + j] == 0) {
#pragma unroll
                for (int i = 0; i < 4; ++i) sf[i][j] = -1e30f;
            }
        }

#pragma unroll
        for (int i = 0; i < 4; ++i) {
            float rm = fmaxf(fmaxf(sf[i][0], sf[i][1]), fmaxf(sf[i][2], sf[i][3]));
#pragma unroll
            for (int off = 1; off < 16; off <<= 1)
                rm = fmaxf(rm, __shfl_xor_sync(0xffffffffu, rm, off));
            const float mn = fmaxf(m_i[i], rm);
            const float corr = exp2_fast(m_i[i] - mn);
            m_i[i] = mn;
            float rs = 0.f;
#pragma unroll
            for (int j = 0; j < 4; ++j) {
                sf[i][j] = exp2_fast(sf[i][j] - mn);
                rs += sf[i][j];
            }
#pragma unroll
            for (int off = 1; off < 16; off <<= 1)
                rs += __shfl_xor_sync(0xffffffffu, rs, off);
            l_i[i] = l_i[i]*corr + rs;
#pragma unroll
            for (int j = 0; j < 4; ++j) acc[i][j] *= corr;
            *(float4*)&Ps[(ty*4 + i)*ATTN_LP + tx*4] =
                make_float4(sf[i][0], sf[i][1], sf[i][2], sf[i][3]);
        }
        __syncthreads();

#pragma unroll 8
        for (int kk = 0; kk < 64; ++kk) {
            float4 v = *(const float4*)&Vs[kk*ATTN_LV + tx*4];
#pragma unroll
            for (int i = 0; i < 4; ++i) {
                float p = Ps[(ty*4 + i)*ATTN_LP + kk];
                acc[i][0] = fmaf(p, v.x, acc[i][0]);
                acc[i][1] = fmaf(p, v.y, acc[i][1]);
                acc[i][2] = fmaf(p, v.z, acc[i][2]);
                acc[i][3] = fmaf(p, v.w, acc[i][3]);
            }
        }
    }

#pragma unroll
    for (int i = 0; i < 4; ++i) {
        const int srow = q0 + ty*4 + i;
        const float inv = 1.f / l_i[i];
        float4 r = make_float4(acc[i][0]*inv, acc[i][1]*inv, acc[i][2]*inv, acc[i][3]*inv);
        *(float4*)&g_ctx[((size_t)b*SEQ + srow)*DIMS + h*HDIM + tx*4] = r;
    }
}

// ---------------------------------------------------------------------------
extern "C" void kernel_launch(void* const* d_in, const int* in_sizes, int n_in,
                              void* d_out, int out_size)
{
    const float* input = (const float*)d_in[0];
    const int*   mask  = (const int*)d_in[1];
    const float* wq = (const float*)d_in[2];
    const float* bq = (const float*)d_in[3];
    const float* wk = (const float*)d_in[4];
    const float* bk = (const float*)d_in[5];
    const float* wv = (const float*)d_in[6];
    const float* bv = (const float*)d_in[7];
    const float* wo = (const float*)d_in[8];
    const float* bo = (const float*)d_in[9];
    float* out = (float*)d_out;
    (void)in_sizes; (void)n_in; (void)out_size;

    const int nx4 = MROWS * DIMS / 4;
    const int nw4 = DIMS * DIMS / 4;

    cvt_kernel<<<(nx4 + 255)/256, 256>>>(input, 0, 0, 0, nx4);
    cvt_kernel<<<(nw4 + 255)/256, 256>>>(wq, 0, 1, 0ull,                nw4);
    cvt_kernel<<<(nw4 + 255)/256, 256>>>(wk, 0, 1, (size_t)DIMS*DIMS,   nw4);
    cvt_kernel<<<(nw4 + 255)/256, 256>>>(wv, 0, 1, (size_t)DIMS*DIMS*2, nw4);
    cvt_kernel<<<(nw4 + 255)/256, 256>>>(wo, 0, 1, (size_t)DIMS*DIMS*3, nw4);

    cudaFuncSetAttribute(gemm_kernel<0>, cudaFuncAttributeMaxDynamicSharedMemorySize, GEMM_DSMEM);
    cudaFuncSetAttribute(gemm_kernel<1>, cudaFuncAttributeMaxDynamicSharedMemorySize, GEMM_DSMEM);
    cudaFuncSetAttribute(gemm_kernel<2>, cudaFuncAttributeMaxDynamicSharedMemorySize, GEMM_DSMEM);
    cudaFuncSetAttribute(gemm_kernel<3>, cudaFuncAttributeMaxDynamicSharedMemorySize, GEMM_DSMEM);

    dim3 ggrid(DIMS/128, MROWS/128);   // 8 x 64

    // q scaled by (1/8)*log2(e) for base-2 softmax
    gemm_kernel<0><<<ggrid, 256, GEMM_DSMEM>>>(0, bq, nullptr, 0.125f * 1.44269504f);
    gemm_kernel<1><<<ggrid, 256, GEMM_DSMEM>>>(1, bk, nullptr, 1.0f);
    gemm_kernel<2><<<ggrid, 256, GEMM_DSMEM>>>(2, bv, nullptr, 1.0f);

    cudaFuncSetAttribute(attn_kernel, cudaFuncAttributeMaxDynamicSharedMemorySize, ATTN_SMEM_BYTES);
    attn_kernel<<<dim3(SEQ/64, BATCH*NHEAD), 256, ATTN_SMEM_BYTES>>>(mask);

    cvt_kernel<<<(nx4 + 255)/256, 256>>>(nullptr, 1, 0, 0, nx4);
    gemm_kernel<3><<<ggrid, 256, GEMM_DSMEM>>>(3, bo, out, 1.0f);
}

// round 5
// speedup vs baseline: 1.9689x; 1.6574x over previous
#include <cuda_runtime.h>
#include <cuda_bf16.h>
#include <cstdint>

#define BATCH 4
#define SEQ   2048
#define DIMS  1024
#define NHEAD 16
#define HDIM  64
#define MROWS (BATCH*SEQ)

typedef unsigned int u32;
typedef unsigned long long u64;

// ---------------- scratch (static device allocations) ----------------
__device__ __nv_bfloat16 g_ah[(size_t)MROWS*DIMS];     // A hi (input, later ctx)
__device__ __nv_bfloat16 g_al[(size_t)MROWS*DIMS];     // A lo
__device__ __nv_bfloat16 g_wh[4ull*DIMS*DIMS];         // wq,wk,wv,wo hi
__device__ __nv_bfloat16 g_wl[4ull*DIMS*DIMS];         // lo
// split Q/K/V in [b,h,s,d] head layout
__device__ __nv_bfloat16 g_qh[(size_t)MROWS*DIMS];
__device__ __nv_bfloat16 g_ql[(size_t)MROWS*DIMS];
__device__ __nv_bfloat16 g_kh[(size_t)MROWS*DIMS];
__device__ __nv_bfloat16 g_kl[(size_t)MROWS*DIMS];
__device__ __nv_bfloat16 g_vh[(size_t)MROWS*DIMS];
__device__ __nv_bfloat16 g_vl[(size_t)MROWS*DIMS];

// ---------------- helpers ----------------
__device__ __forceinline__ u32 smem_u32(const void* p) {
    u32 a;
    asm("{ .reg .u64 t; cvta.to.shared.u64 t, %1; cvt.u32.u64 %0, t; }" : "=r"(a) : "l"(p));
    return a;
}
#define CP_ASYNC16(d, g) \
    asm volatile("cp.async.cg.shared.global [%0], [%1], 16;" :: "r"(d), "l"(g) : "memory")
#define CP_COMMIT() asm volatile("cp.async.commit_group;" ::: "memory")
#define CP_WAIT1()  asm volatile("cp.async.wait_group 1;" ::: "memory")
#define CP_WAIT0()  asm volatile("cp.async.wait_group 0;" ::: "memory")

#define LDSM4(r0, r1, r2, r3, a) \
    asm volatile("ldmatrix.sync.aligned.m8n8.x4.shared.b16 {%0,%1,%2,%3}, [%4];" \
                 : "=r"(r0), "=r"(r1), "=r"(r2), "=r"(r3) : "r"(a))
#define LDSM4T(r0, r1, r2, r3, a) \
    asm volatile("ldmatrix.sync.aligned.m8n8.x4.trans.shared.b16 {%0,%1,%2,%3}, [%4];" \
                 : "=r"(r0), "=r"(r1), "=r"(r2), "=r"(r3) : "r"(a))

#define MMA_BF16(d, a, b0, b1) \
    asm volatile("mma.sync.aligned.m16n8k16.row.col.f32.bf16.bf16.f32 " \
                 "{%0,%1,%2,%3}, {%4,%5,%6,%7}, {%8,%9}, {%0,%1,%2,%3};" \
                 : "+f"((d)[0]), "+f"((d)[1]), "+f"((d)[2]), "+f"((d)[3]) \
                 : "r"((a)[0]), "r"((a)[1]), "r"((a)[2]), "r"((a)[3]), \
                   "r"(b0), "r"(b1))

__device__ __forceinline__ u32 pack_bf16(float a, float b) {
    __nv_bfloat162 t = __floats2bfloat162_rn(a, b);
    return *(u32*)&t;
}

// Fast 2^t
__device__ __forceinline__ float exp2_fast(float t) {
    t = fmaxf(t, -126.0f);
    float r = t + 12582912.0f;
    int   i = __float_as_int(r) << 23;
    float f = t - (r - 12582912.0f);
    float p = fmaf(f, 0.00961813f, 0.05550411f);
    p = fmaf(f, p, 0.24022651f);
    p = fmaf(f, p, 0.69314718f);
    p = fmaf(f, p, 1.0f);
    return __int_as_float(__float_as_int(p) + i);
}

// ---------------- fp32 -> bf16 hi/lo split ----------------
__global__ void cvt_kernel(const float* __restrict__ src,
                           int dst_sel, size_t dst_off, int n4)
{
    __nv_bfloat16* H = (dst_sel == 0 ? g_ah : g_wh) + dst_off;
    __nv_bfloat16* L = (dst_sel == 0 ? g_al : g_wl) + dst_off;
    int i = blockIdx.x * 256 + threadIdx.x;
    if (i >= n4) return;
    float4 v = ((const float4*)src)[i];
    float h0 = __bfloat162float(__float2bfloat16_rn(v.x));
    float h1 = __bfloat162float(__float2bfloat16_rn(v.y));
    float h2 = __bfloat162float(__float2bfloat16_rn(v.z));
    float h3 = __bfloat162float(__float2bfloat16_rn(v.w));
    ((u32*)H)[i*2+0] = pack_bf16(h0, h1);
    ((u32*)H)[i*2+1] = pack_bf16(h2, h3);
    ((u32*)L)[i*2+0] = pack_bf16(v.x - h0, v.y - h1);
    ((u32*)L)[i*2+1] = pack_bf16(v.z - h2, v.w - h3);
}

// ---------------- mma.sync split-bf16 GEMM ----------------
// C[m0:+128, n0:+128] = scale*(A @ W^T + bias), via Ah*Bh + Ah*Bl + Al*Bh.
// OUT_SEL 0/1/2 -> split bf16 to g_q*/g_k*/g_v* in [b,h,s,d]; 3 -> fp32 outp.
#define GSTR   40
#define MATB   (128*GSTR*2)
#define STAGEB (4*MATB)
#define GEMM_DSMEM (2*STAGEB)

template<int OUT_SEL>
__global__ __launch_bounds__(256) void gemm_kernel(
    int widx, const float* __restrict__ bias, float* __restrict__ outp, float scale)
{
    extern __shared__ __align__(16) char dyn[];
    __shared__ float s_bias[128];

    const int tid = threadIdx.x, wid = tid >> 5, lane = tid & 31;
    const int m0 = blockIdx.y * 128, n0 = blockIdx.x * 128;
    const int wm = (wid >> 2) * 64, wn = (wid & 3) * 32;
    const u32 sbase = smem_u32(dyn);

    if (tid < 128) s_bias[tid] = bias[n0 + tid];

    const __nv_bfloat16* __restrict__ Wh = g_wh + (size_t)widx * DIMS * DIMS;
    const __nv_bfloat16* __restrict__ Wl = g_wl + (size_t)widx * DIMS * DIMS;

    const int lmat = tid >> 6;
    const int lt   = tid & 63;
    const __nv_bfloat16* lsrc =
        (lmat == 0) ? (g_ah + (size_t)m0 * DIMS) :
        (lmat == 1) ? (g_al + (size_t)m0 * DIMS) :
        (lmat == 2) ? (Wh   + (size_t)n0 * DIMS) :
                      (Wl   + (size_t)n0 * DIMS);

    auto load_stage = [&](int s, int k0) {
        u32 mb = sbase + s * STAGEB + lmat * MATB;
#pragma unroll
        for (int c = 0; c < 8; ++c) {
            int row = lt * 2 + (c >> 2);
            int cc = c & 3;
            u64 g = (u64)__cvta_generic_to_global(lsrc + (size_t)row * DIMS + k0 + cc * 8);
            CP_ASYNC16(mb + row * (GSTR*2) + cc * 16, g);
        }
        CP_COMMIT();
    };

    float acc[4][4][4];
#pragma unroll
    for (int i = 0; i < 4; ++i)
#pragma unroll
        for (int j = 0; j < 4; ++j)
#pragma unroll
            for (int r = 0; r < 4; ++r) acc[i][j][r] = 0.f;

    const int NIT = DIMS / 32;
    load_stage(0, 0);

    const int lrow = lane & 15;
    const int lkof = ((lane >> 4) & 1) * 8;

    for (int it = 0; it < NIT; ++it) {
        if (it + 1 < NIT) { load_stage((it + 1) & 1, (it + 1) * 32); CP_WAIT1(); }
        else              { CP_WAIT0(); }
        __syncthreads();

        const u32 st  = sbase + (it & 1) * STAGEB;
        const u32 pAh = st, pAl = st + MATB, pBh = st + 2*MATB, pBl = st + 3*MATB;

#pragma unroll
        for (int ks = 0; ks < 2; ++ks) {
            const int kh = ks * 16 + lkof;
            u32 ah[4][4], al[4][4], bh[2][4], bl[2][4];
#pragma unroll
            for (int ti = 0; ti < 4; ++ti) {
                u32 ra = (u32)((wm + ti*16 + lrow) * (GSTR*2) + kh*2);
                LDSM4(ah[ti][0], ah[ti][1], ah[ti][2], ah[ti][3], pAh + ra);
                LDSM4(al[ti][0], al[ti][1], al[ti][2], al[ti][3], pAl + ra);
            }
#pragma unroll
            for (int g = 0; g < 2; ++g) {
                u32 rb = (u32)((wn + g*16 + lrow) * (GSTR*2) + kh*2);
                LDSM4(bh[g][0], bh[g][1], bh[g][2], bh[g][3], pBh + rb);
                LDSM4(bl[g][0], bl[g][1], bl[g][2], bl[g][3], pBl + rb);
            }
#pragma unroll
            for (int ti = 0; ti < 4; ++ti) {
#pragma unroll
                for (int nj = 0; nj < 4; ++nj) {
                    const int g = nj >> 1, o = nj & 1;
                    MMA_BF16(acc[ti][nj], ah[ti], bh[g][o],   bh[g][o+2]);
                    MMA_BF16(acc[ti][nj], ah[ti], bl[g][o],   bl[g][o+2]);
                    MMA_BF16(acc[ti][nj], al[ti], bh[g][o],   bh[g][o+2]);
                }
            }
        }
        __syncthreads();
    }

#pragma unroll
    for (int ti = 0; ti < 4; ++ti) {
#pragma unroll
        for (int nj = 0; nj < 4; ++nj) {
            const int col = wn + nj*8 + (lane & 3)*2;
            const int r0  = m0 + wm + ti*16 + (lane >> 2);
            const float b0 = s_bias[col], b1 = s_bias[col + 1];
            float v0 = (acc[ti][nj][0] + b0) * scale;
            float v1 = (acc[ti][nj][1] + b1) * scale;
            float v2 = (acc[ti][nj][2] + b0) * scale;
            float v3 = (acc[ti][nj][3] + b1) * scale;
            if (OUT_SEL < 3) {
                __nv_bfloat16* H = (OUT_SEL == 0) ? g_qh : (OUT_SEL == 1) ? g_kh : g_vh;
                __nv_bfloat16* L = (OUT_SEL == 0) ? g_ql : (OUT_SEL == 1) ? g_kl : g_vl;
                const int nglob = n0 + col;
                const int hh = nglob >> 6, dd = nglob & 63;
                const int bb = r0 >> 11, ss = r0 & 2047;
                size_t base = (((size_t)bb*NHEAD + hh)*SEQ + ss)*HDIM + dd;
                float h0 = __bfloat162float(__float2bfloat16_rn(v0));
                float h1 = __bfloat162float(__float2bfloat16_rn(v1));
                float h2 = __bfloat162float(__float2bfloat16_rn(v2));
                float h3 = __bfloat162float(__float2bfloat16_rn(v3));
                *(u32*)&H[base]          = pack_bf16(h0, h1);
                *(u32*)&L[base]          = pack_bf16(v0 - h0, v1 - h1);
                *(u32*)&H[base + 8*HDIM] = pack_bf16(h2, h3);
                *(u32*)&L[base + 8*HDIM] = pack_bf16(v2 - h2, v3 - h3);
            } else {
                *(float2*)&outp[(size_t)r0 * DIMS + n0 + col]     = make_float2(v0, v1);
                *(float2*)&outp[(size_t)(r0+8) * DIMS + n0 + col] = make_float2(v2, v3);
            }
        }
    }
}

// ---------------- tensorized flash attention (split bf16) ----------------
// CTA: one (b,h) x 128 q-rows, 8 warps (16 q each). k-tiles of 64 keys,
// double-buffered Kh/Kl/Vh/Vl via cp.async. S and P live in registers.
#define NKT    (SEQ/64)
#define KVROWB 144                 // 72 halves: conflict-free ldmatrix stride
#define MATKB  (64*KVROWB)         // 9216 B per 64x64 bf16 matrix
#define STGB   (4*MATKB)           // 36864 B per stage
#define ATTN_DSMEM (2*STGB)

__global__ __launch_bounds__(256, 1) void attn_kernel(const int* __restrict__ mask)
{
    extern __shared__ __align__(16) char dyn[];
    __shared__ int Ms[2][64];
    const u32 sbase = smem_u32(dyn);
    const int tid = threadIdx.x, wid = tid >> 5, lane = tid & 31;
    const int bh = blockIdx.y, b = bh >> 4, h = bh & 15;
    const int q0 = blockIdx.x * 128;

    const __nv_bfloat16* __restrict__ Qh = g_qh + (size_t)bh*SEQ*HDIM + (size_t)q0*HDIM;
    const __nv_bfloat16* __restrict__ Ql = g_ql + (size_t)bh*SEQ*HDIM + (size_t)q0*HDIM;
    const __nv_bfloat16* __restrict__ Kh = g_kh + (size_t)bh*SEQ*HDIM;
    const __nv_bfloat16* __restrict__ Kl = g_kl + (size_t)bh*SEQ*HDIM;
    const __nv_bfloat16* __restrict__ Vh = g_vh + (size_t)bh*SEQ*HDIM;
    const __nv_bfloat16* __restrict__ Vl = g_vl + (size_t)bh*SEQ*HDIM;

    // --- prologue: stage Q into stage-1 region (reused for KV after extraction)
    const u32 qbase = sbase + STGB;
#pragma unroll
    for (int i = 0; i < 8; ++i) {
        int c = tid + i*256;                // 2048 16B-chunks (Qh then Ql)
        int mat = c >> 10, rem = c & 1023, row = rem >> 3, cc = rem & 7;
        const __nv_bfloat16* s = (mat ? Ql : Qh) + (size_t)row*HDIM + cc*8;
        CP_ASYNC16(qbase + mat*(128*KVROWB) + row*KVROWB + cc*16,
                   (u64)__cvta_generic_to_global(s));
    }
    CP_COMMIT();

    auto load_kv = [&](int stg, int kt) {
        const u32 sb = sbase + stg*STGB;
#pragma unroll
        for (int i = 0; i < 8; ++i) {
            int c = tid + i*256;            // 2048 chunks over Kh,Kl,Vh,Vl
            int mat = c >> 9, rem = c & 511, row = rem >> 3, cc = rem & 7;
            const __nv_bfloat16* s =
                ((mat == 0) ? Kh : (mat == 1) ? Kl : (mat == 2) ? Vh : Vl)
                + (size_t)(kt*64 + row)*HDIM + cc*8;
            CP_ASYNC16(sb + mat*MATKB + row*KVROWB + cc*16,
                       (u64)__cvta_generic_to_global(s));
        }
        CP_COMMIT();
    };
    load_kv(0, 0);
    if (tid < 64) Ms[0][tid] = mask[b*SEQ + tid];

    CP_WAIT1();                    // Q group done (KV0 may still be in flight)
    __syncthreads();

    // --- extract Q fragments (persist in registers)
    u32 qfh[4][4], qfl[4][4];
#pragma unroll
    for (int ks = 0; ks < 4; ++ks) {
        u32 ra = qbase + (u32)((wid*16 + (lane & 15))*KVROWB
                               + (ks*16 + ((lane >> 4) & 1)*8)*2);
        LDSM4(qfh[ks][0], qfh[ks][1], qfh[ks][2], qfh[ks][3], ra);
        LDSM4(qfl[ks][0], qfl[ks][1], qfl[ks][2], qfl[ks][3], ra + 128*KVROWB);
    }
    __syncthreads();               // stage-1 region free for KV tile 1

    float O[8][4];
#pragma unroll
    for (int dt = 0; dt < 8; ++dt)
#pragma unroll
        for (int r = 0; r < 4; ++r) O[dt][r] = 0.f;
    float m0v = -1e30f, m1v = -1e30f, l0v = 0.f, l1v = 0.f;

    for (int kt = 0; kt < NKT; ++kt) {
        const int stg = kt & 1;
        if (kt + 1 < NKT) {
            load_kv(stg ^ 1, kt + 1);
            if (tid < 64) Ms[(kt+1) & 1][tid] = mask[b*SEQ + (kt+1)*64 + tid];
            CP_WAIT1();
        } else {
            CP_WAIT0();
        }
        __syncthreads();

        const u32 kb = sbase + stg*STGB;

        // ---- S = Q K^T (3-term split) ----
        float S[8][4];
#pragma unroll
        for (int nt = 0; nt < 8; ++nt)
#pragma unroll
            for (int r = 0; r < 4; ++r) S[nt][r] = 0.f;

#pragma unroll
        for (int ks = 0; ks < 4; ++ks) {
            u32 kfh[4][4], kfl[4][4];
#pragma unroll
            for (int g = 0; g < 4; ++g) {
                u32 rb = kb + (u32)((g*16 + (lane & 15))*KVROWB
                                    + (ks*16 + ((lane >> 4) & 1)*8)*2);
                LDSM4(kfh[g][0], kfh[g][1], kfh[g][2], kfh[g][3], rb);
                LDSM4(kfl[g][0], kfl[g][1], kfl[g][2], kfl[g][3], rb + MATKB);
            }
#pragma unroll
            for (int nt = 0; nt < 8; ++nt) {
                const int g = nt >> 1, o = nt & 1;
                MMA_BF16(S[nt], qfh[ks], kfh[g][o], kfh[g][o+2]);
                MMA_BF16(S[nt], qfh[ks], kfl[g][o], kfl[g][o+2]);
                MMA_BF16(S[nt], qfl[ks], kfh[g][o], kfh[g][o+2]);
            }
        }

        // ---- mask ----
        const int c0 = (lane & 3) * 2;
#pragma unroll
        for (int nt = 0; nt < 8; ++nt) {
            if (Ms[stg][nt*8 + c0]     == 0) { S[nt][0] = -1e30f; S[nt][2] = -1e30f; }
            if (Ms[stg][nt*8 + c0 + 1] == 0) { S[nt][1] = -1e30f; S[nt][3] = -1e30f; }
        }

        // ---- online softmax (base-2, rows r=lane>>2 and r+8) ----
        float mx0 = -1e30f, mx1 = -1e30f;
#pragma unroll
        for (int nt = 0; nt < 8; ++nt) {
            mx0 = fmaxf(mx0, fmaxf(S[nt][0], S[nt][1]));
            mx1 = fmaxf(mx1, fmaxf(S[nt][2], S[nt][3]));
        }
#pragma unroll
        for (int off = 1; off < 4; off <<= 1) {
            mx0 = fmaxf(mx0, __shfl_xor_sync(0xffffffffu, mx0, off));
            mx1 = fmaxf(mx1, __shfl_xor_sync(0xffffffffu, mx1, off));
        }
        const float mn0 = fmaxf(m0v, mx0), mn1 = fmaxf(m1v, mx1);
        const float cr0 = exp2_fast(m0v - mn0), cr1 = exp2_fast(m1v - mn1);
        m0v = mn0; m1v = mn1;

        float s0 = 0.f, s1 = 0.f;
        u32 pa[4][4], pl[4][4];
#pragma unroll
        for (int t = 0; t < 4; ++t) {
#pragma unroll
            for (int hf = 0; hf < 2; ++hf) {
                const int nt = 2*t + hf;
                float p0 = exp2_fast(S[nt][0] - mn0);
                float p1 = exp2_fast(S[nt][1] - mn0);
                float p2 = exp2_fast(S[nt][2] - mn1);
                float p3 = exp2_fast(S[nt][3] - mn1);
                s0 += p0 + p1; s1 += p2 + p3;
                float h0 = __bfloat162float(__float2bfloat16_rn(p0));
                float h1 = __bfloat162float(__float2bfloat16_rn(p1));
                float h2 = __bfloat162float(__float2bfloat16_rn(p2));
                float h3 = __bfloat162float(__float2bfloat16_rn(p3));
                pa[t][2*hf]     = pack_bf16(h0, h1);
                pa[t][2*hf + 1] = pack_bf16(h2, h3);
                pl[t][2*hf]     = pack_bf16(p0 - h0, p1 - h1);
                pl[t][2*hf + 1] = pack_bf16(p2 - h2, p3 - h3);
            }
        }
#pragma unroll
        for (int off = 1; off < 4; off <<= 1) {
            s0 += __shfl_xor_sync(0xffffffffu, s0, off);
            s1 += __shfl_xor_sync(0xffffffffu, s1, off);
        }
        l0v = l0v*cr0 + s0;
        l1v = l1v*cr1 + s1;
#pragma unroll
        for (int dt = 0; dt < 8; ++dt) {
            O[dt][0] *= cr0; O[dt][1] *= cr0;
            O[dt][2] *= cr1; O[dt][3] *= cr1;
        }

        // ---- O += P V (3-term split), V via ldmatrix.trans ----
        const u32 vb = kb + 2*MATKB;
#pragma unroll
        for (int t = 0; t < 4; ++t) {
            u32 vfh[4][4], vfl[4][4];
#pragma unroll
            for (int dg = 0; dg < 4; ++dg) {
                u32 rb = vb + (u32)((t*16 + (lane & 15))*KVROWB
                                    + (dg*16 + ((lane >> 4) & 1)*8)*2);
                LDSM4T(vfh[dg][0], vfh[dg][1], vfh[dg][2], vfh[dg][3], rb);
                LDSM4T(vfl[dg][0], vfl[dg][1], vfl[dg][2], vfl[dg][3], rb + MATKB);
            }
#pragma unroll
            for (int dt = 0; dt < 8; ++dt) {
                const int g = dt >> 1, o = (dt & 1) * 2;
                MMA_BF16(O[dt], pa[t], vfh[g][o], vfh[g][o+1]);
                MMA_BF16(O[dt], pa[t], vfl[g][o], vfl[g][o+1]);
                MMA_BF16(O[dt], pl[t], vfh[g][o], vfh[g][o+1]);
            }
        }
        __syncthreads();           // all warps done with this stage before reuse
    }

    // ---- epilogue: normalize, write ctx as split bf16 [m, h*64+d] ----
    const float i0 = 1.f / l0v, i1 = 1.f / l1v;
    const int r = lane >> 2;
    const size_t row0 = (size_t)b*SEQ + q0 + wid*16 + r;
#pragma unroll
    for (int dt = 0; dt < 8; ++dt) {
        const int col = h*HDIM + dt*8 + (lane & 3)*2;
        float v0 = O[dt][0]*i0, v1 = O[dt][1]*i0;
        float v2 = O[dt][2]*i1, v3 = O[dt][3]*i1;
        float h0 = __bfloat162float(__float2bfloat16_rn(v0));
        float h1 = __bfloat162float(__float2bfloat16_rn(v1));
        float h2 = __bfloat162float(__float2bfloat16_rn(v2));
        float h3 = __bfloat162float(__float2bfloat16_rn(v3));
        *(u32*)&g_ah[row0*DIMS + col]       = pack_bf16(h0, h1);
        *(u32*)&g_al[row0*DIMS + col]       = pack_bf16(v0 - h0, v1 - h1);
        *(u32*)&g_ah[(row0+8)*DIMS + col]   = pack_bf16(h2, h3);
        *(u32*)&g_al[(row0+8)*DIMS + col]   = pack_bf16(v2 - h2, v3 - h3);
    }
}

// ---------------------------------------------------------------------------
extern "C" void kernel_launch(void* const* d_in, const int* in_sizes, int n_in,
                              void* d_out, int out_size)
{
    const float* input = (const float*)d_in[0];
    const int*   mask  = (const int*)d_in[1];
    const float* wq = (const float*)d_in[2];
    const float* bq = (const float*)d_in[3];
    const float* wk = (const float*)d_in[4];
    const float* bk = (const float*)d_in[5];
    const float* wv = (const float*)d_in[6];
    const float* bv = (const float*)d_in[7];
    const float* wo = (const float*)d_in[8];
    const float* bo = (const float*)d_in[9];
    float* out = (float*)d_out;
    (void)in_sizes; (void)n_in; (void)out_size;

    const int nx4 = MROWS * DIMS / 4;
    const int nw4 = DIMS * DIMS / 4;

    cvt_kernel<<<(nx4 + 255)/256, 256>>>(input, 0, 0, nx4);
    cvt_kernel<<<(nw4 + 255)/256, 256>>>(wq, 1, 0ull,                nw4);
    cvt_kernel<<<(nw4 + 255)/256, 256>>>(wk, 1, (size_t)DIMS*DIMS,   nw4);
    cvt_kernel<<<(nw4 + 255)/256, 256>>>(wv, 1, (size_t)DIMS*DIMS*2, nw4);
    cvt_kernel<<<(nw4 + 255)/256, 256>>>(wo, 1, (size_t)DIMS*DIMS*3, nw4);

    cudaFuncSetAttribute(gemm_kernel<0>, cudaFuncAttributeMaxDynamicSharedMemorySize, GEMM_DSMEM);
    cudaFuncSetAttribute(gemm_kernel<1>, cudaFuncAttributeMaxDynamicSharedMemorySize, GEMM_DSMEM);
    cudaFuncSetAttribute(gemm_kernel<2>, cudaFuncAttributeMaxDynamicSharedMemorySize, GEMM_DSMEM);
    cudaFuncSetAttribute(gemm_kernel<3>, cudaFuncAttributeMaxDynamicSharedMemorySize, GEMM_DSMEM);

    dim3 ggrid(DIMS/128, MROWS/128);

    // q pre-scaled by (1/8)*log2(e) for base-2 softmax
    gemm_kernel<0><<<ggrid, 256, GEMM_DSMEM>>>(0, bq, nullptr, 0.125f * 1.44269504f);
    gemm_kernel<1><<<ggrid, 256, GEMM_DSMEM>>>(1, bk, nullptr, 1.0f);
    gemm_kernel<2><<<ggrid, 256, GEMM_DSMEM>>>(2, bv, nullptr, 1.0f);

    cudaFuncSetAttribute(attn_kernel, cudaFuncAttributeMaxDynamicSharedMemorySize, ATTN_DSMEM);
    attn_kernel<<<dim3(SEQ/128, BATCH*NHEAD), 256, ATTN_DSMEM>>>(mask);

    gemm_kernel<3><<<ggrid, 256, GEMM_DSMEM>>>(3, bo, out, 1.0f);
}

// round 6
// speedup vs baseline: 2.9971x; 1.5223x over previous
#include <cuda_runtime.h>
#include <cuda_fp16.h>
#include <cstdint>

#define BATCH 4
#define SEQ   2048
#define DIMS  1024
#define NHEAD 16
#define HDIM  64
#define MROWS (BATCH*SEQ)

typedef unsigned int u32;
typedef unsigned long long u64;

// ---------------- scratch (static device allocations) ----------------
__device__ __half g_a [(size_t)MROWS*DIMS];      // A single fp16 (input, later ctx)
__device__ __half g_wh[4ull*DIMS*DIMS];          // weights hi
__device__ __half g_wl[4ull*DIMS*DIMS];          // weights lo
__device__ __half g_qh[(size_t)MROWS*DIMS];      // Q split [b,h,s,d]
__device__ __half g_ql[(size_t)MROWS*DIMS];
__device__ __half g_kh[(size_t)MROWS*DIMS];      // K split
__device__ __half g_kl[(size_t)MROWS*DIMS];
__device__ __half g_vh[(size_t)MROWS*DIMS];      // V single

// ---------------- helpers ----------------
__device__ __forceinline__ u32 smem_u32(const void* p) {
    u32 a;
    asm("{ .reg .u64 t; cvta.to.shared.u64 t, %1; cvt.u32.u64 %0, t; }" : "=r"(a) : "l"(p));
    return a;
}
#define CP_ASYNC16(d, g) \
    asm volatile("cp.async.cg.shared.global [%0], [%1], 16;" :: "r"(d), "l"(g) : "memory")
#define CP_COMMIT() asm volatile("cp.async.commit_group;" ::: "memory")
#define CP_WAIT1()  asm volatile("cp.async.wait_group 1;" ::: "memory")
#define CP_WAIT0()  asm volatile("cp.async.wait_group 0;" ::: "memory")

#define LDSM4(r0, r1, r2, r3, a) \
    asm volatile("ldmatrix.sync.aligned.m8n8.x4.shared.b16 {%0,%1,%2,%3}, [%4];" \
                 : "=r"(r0), "=r"(r1), "=r"(r2), "=r"(r3) : "r"(a))
#define LDSM4T(r0, r1, r2, r3, a) \
    asm volatile("ldmatrix.sync.aligned.m8n8.x4.trans.shared.b16 {%0,%1,%2,%3}, [%4];" \
                 : "=r"(r0), "=r"(r1), "=r"(r2), "=r"(r3) : "r"(a))

#define MMA_F16(d, a, b0, b1) \
    asm volatile("mma.sync.aligned.m16n8k16.row.col.f32.f16.f16.f32 " \
                 "{%0,%1,%2,%3}, {%4,%5,%6,%7}, {%8,%9}, {%0,%1,%2,%3};" \
                 : "+f"((d)[0]), "+f"((d)[1]), "+f"((d)[2]), "+f"((d)[3]) \
                 : "r"((a)[0]), "r"((a)[1]), "r"((a)[2]), "r"((a)[3]), \
                   "r"(b0), "r"(b1))

__device__ __forceinline__ u32 pack_h16(float a, float b) {
    __half2 t = __floats2half2_rn(a, b);
    return *(u32*)&t;
}

// Fast 2^t
__device__ __forceinline__ float exp2_fast(float t) {
    t = fmaxf(t, -126.0f);
    float r = t + 12582912.0f;
    int   i = __float_as_int(r) << 23;
    float f = t - (r - 12582912.0f);
    float p = fmaf(f, 0.00961813f, 0.05550411f);
    p = fmaf(f, p, 0.24022651f);
    p = fmaf(f, p, 0.69314718f);
    p = fmaf(f, p, 1.0f);
    return __int_as_float(__float_as_int(p) + i);
}

// ---------------- conversions ----------------
__global__ void cvt_single(const float* __restrict__ src, int n4)
{
    int i = blockIdx.x * 256 + threadIdx.x;
    if (i >= n4) return;
    float4 v = ((const float4*)src)[i];
    ((u32*)g_a)[i*2+0] = pack_h16(v.x, v.y);
    ((u32*)g_a)[i*2+1] = pack_h16(v.z, v.w);
}

__global__ void cvt_split(const float* __restrict__ src, size_t off, int n4)
{
    __half* H = g_wh + off;
    __half* L = g_wl + off;
    int i = blockIdx.x * 256 + threadIdx.x;
    if (i >= n4) return;
    float4 v = ((const float4*)src)[i];
    float h0 = __half2float(__float2half_rn(v.x));
    float h1 = __half2float(__float2half_rn(v.y));
    float h2 = __half2float(__float2half_rn(v.z));
    float h3 = __half2float(__float2half_rn(v.w));
    ((u32*)H)[i*2+0] = pack_h16(h0, h1);
    ((u32*)H)[i*2+1] = pack_h16(h2, h3);
    ((u32*)L)[i*2+0] = pack_h16(v.x - h0, v.y - h1);
    ((u32*)L)[i*2+1] = pack_h16(v.z - h2, v.w - h3);
}

// ---------------- fp16 2-term GEMM ----------------
// C[m0:+256, n0:+128] = scale*(A @ (Wh+Wl)^T + bias), A single fp16.
// 256 threads, warp grid 4(m)x2(n), warp tile 64x64, BK=32, 2-stage cp.async.
#define GSTR   40                       // halves per smem row (32 + 8 pad)
#define A_MATB (256*GSTR*2)             // 20480
#define B_MATB (128*GSTR*2)             // 10240
#define STAGEB (A_MATB + 2*B_MATB)      // 40960
#define GEMM_DSMEM (2*STAGEB)           // 81920

template<int OUT_SEL>  // 0=Q(split) 1=K(split) 2=V(single) 3=fp32 out
__global__ __launch_bounds__(256, 1) void gemm_kernel(
    int widx, const float* __restrict__ bias, float* __restrict__ outp, float scale)
{
    extern __shared__ __align__(16) char dyn[];
    __shared__ float s_bias[128];

    const int tid = threadIdx.x, wid = tid >> 5, lane = tid & 31;
    const int m0 = blockIdx.y * 256, n0 = blockIdx.x * 128;
    const int wm = (wid >> 1) * 64, wn = (wid & 1) * 64;
    const u32 sbase = smem_u32(dyn);

    if (tid < 128) s_bias[tid] = bias[n0 + tid];

    const __half* __restrict__ Asrc = g_a  + (size_t)m0 * DIMS;
    const __half* __restrict__ Bh   = g_wh + (size_t)widx * DIMS * DIMS + (size_t)n0 * DIMS;
    const __half* __restrict__ Bl   = g_wl + (size_t)widx * DIMS * DIMS + (size_t)n0 * DIMS;

    auto load_stage = [&](int s, int k0) {
        const u32 sb = sbase + s * STAGEB;
        if (tid < 128) {
#pragma unroll
            for (int i = 0; i < 8; ++i) {
                int c = i * 128 + tid;              // 0..1023
                int row = c >> 2, col = c & 3;
                CP_ASYNC16(sb + row * (GSTR*2) + col * 16,
                           (u64)__cvta_generic_to_global(Asrc + (size_t)row * DIMS + k0 + col * 8));
            }
        } else if (tid < 192) {
            int t = tid - 128;
#pragma unroll
            for (int i = 0; i < 8; ++i) {
                int c = i * 64 + t;                 // 0..511
                int row = c >> 2, col = c & 3;
                CP_ASYNC16(sb + A_MATB + row * (GSTR*2) + col * 16,
                           (u64)__cvta_generic_to_global(Bh + (size_t)row * DIMS + k0 + col * 8));
            }
        } else {
            int t = tid - 192;
#pragma unroll
            for (int i = 0; i < 8; ++i) {
                int c = i * 64 + t;
                int row = c >> 2, col = c & 3;
                CP_ASYNC16(sb + A_MATB + B_MATB + row * (GSTR*2) + col * 16,
                           (u64)__cvta_generic_to_global(Bl + (size_t)row * DIMS + k0 + col * 8));
            }
        }
        CP_COMMIT();
    };

    float acc[4][8][4];
#pragma unroll
    for (int i = 0; i < 4; ++i)
#pragma unroll
        for (int j = 0; j < 8; ++j)
#pragma unroll
            for (int r = 0; r < 4; ++r) acc[i][j][r] = 0.f;

    const int NIT = DIMS / 32;
    load_stage(0, 0);

    const int lrow = lane & 15;
    const int lkof = ((lane >> 4) & 1) * 8;

    for (int it = 0; it < NIT; ++it) {
        if (it + 1 < NIT) { load_stage((it + 1) & 1, (it + 1) * 32); CP_WAIT1(); }
        else              { CP_WAIT0(); }
        __syncthreads();

        const u32 st = sbase + (it & 1) * STAGEB;
#pragma unroll
        for (int ks = 0; ks < 2; ++ks) {
            const int kh = ks * 16 + lkof;
            u32 a[4][4], bh[4][4], bl[4][4];
#pragma unroll
            for (int ti = 0; ti < 4; ++ti) {
                u32 ra = st + (u32)((wm + ti*16 + lrow) * (GSTR*2) + kh*2);
                LDSM4(a[ti][0], a[ti][1], a[ti][2], a[ti][3], ra);
            }
#pragma unroll
            for (int g = 0; g < 4; ++g) {
                u32 rb = st + A_MATB + (u32)((wn + g*16 + lrow) * (GSTR*2) + kh*2);
                LDSM4(bh[g][0], bh[g][1], bh[g][2], bh[g][3], rb);
                LDSM4(bl[g][0], bl[g][1], bl[g][2], bl[g][3], rb + B_MATB);
            }
#pragma unroll
            for (int ti = 0; ti < 4; ++ti) {
#pragma unroll
                for (int nj = 0; nj < 8; ++nj) {
                    const int g = nj >> 1, o = nj & 1;
                    MMA_F16(acc[ti][nj], a[ti], bh[g][o], bh[g][o+2]);
                    MMA_F16(acc[ti][nj], a[ti], bl[g][o], bl[g][o+2]);
                }
            }
        }
        __syncthreads();
    }

#pragma unroll
    for (int ti = 0; ti < 4; ++ti) {
#pragma unroll
        for (int nj = 0; nj < 8; ++nj) {
            const int col = wn + nj*8 + (lane & 3)*2;
            const int r0  = m0 + wm + ti*16 + (lane >> 2);
            const float b0 = s_bias[col], b1 = s_bias[col + 1];
            float v0 = (acc[ti][nj][0] + b0) * scale;
            float v1 = (acc[ti][nj][1] + b1) * scale;
            float v2 = (acc[ti][nj][2] + b0) * scale;
            float v3 = (acc[ti][nj][3] + b1) * scale;
            if (OUT_SEL <= 2) {
                const int nglob = n0 + col;
                const int hh = nglob >> 6, dd = nglob & 63;
                const int bb = r0 >> 11, ss = r0 & 2047;
                const size_t base = (((size_t)bb*NHEAD + hh)*SEQ + ss)*HDIM + dd;
                if (OUT_SEL == 2) {
                    *(u32*)&g_vh[base]          = pack_h16(v0, v1);
                    *(u32*)&g_vh[base + 8*HDIM] = pack_h16(v2, v3);
                } else {
                    __half* H = (OUT_SEL == 0) ? g_qh : g_kh;
                    __half* L = (OUT_SEL == 0) ? g_ql : g_kl;
                    float h0 = __half2float(__float2half_rn(v0));
                    float h1 = __half2float(__float2half_rn(v1));
                    float h2 = __half2float(__float2half_rn(v2));
                    float h3 = __half2float(__float2half_rn(v3));
                    *(u32*)&H[base]          = pack_h16(h0, h1);
                    *(u32*)&L[base]          = pack_h16(v0 - h0, v1 - h1);
                    *(u32*)&H[base + 8*HDIM] = pack_h16(h2, h3);
                    *(u32*)&L[base + 8*HDIM] = pack_h16(v2 - h2, v3 - h3);
                }
            } else {
                *(float2*)&outp[(size_t)r0 * DIMS + n0 + col]     = make_float2(v0, v1);
                *(float2*)&outp[(size_t)(r0+8) * DIMS + n0 + col] = make_float2(v2, v3);
            }
        }
    }
}

// ---------------- tensorized flash attention (fp16) ----------------
// S = Qh Kh + Qh Kl + Ql Kh (3-term); O += Ph V + Pl V (2-term, V single).
#define NKT    (SEQ/64)
#define KVROWB 144
#define MATKB  (64*KVROWB)          // 9216
#define STGB   (3*MATKB)            // 27648: Kh, Kl, Vh
#define QMATB  (128*KVROWB)         // 18432
#define ATTN_DSMEM (2*STGB + 2*QMATB)   // 92160

__global__ __launch_bounds__(256, 1) void attn_kernel(const int* __restrict__ mask)
{
    extern __shared__ __align__(16) char dyn[];
    __shared__ int Ms[2][64];
    const u32 sbase = smem_u32(dyn);
    const int tid = threadIdx.x, wid = tid >> 5, lane = tid & 31;
    const int bh = blockIdx.y, b = bh >> 4, h = bh & 15;
    const int q0 = blockIdx.x * 128;

    const __half* __restrict__ Qh = g_qh + (size_t)bh*SEQ*HDIM + (size_t)q0*HDIM;
    const __half* __restrict__ Ql = g_ql + (size_t)bh*SEQ*HDIM + (size_t)q0*HDIM;
    const __half* __restrict__ Kh = g_kh + (size_t)bh*SEQ*HDIM;
    const __half* __restrict__ Kl = g_kl + (size_t)bh*SEQ*HDIM;
    const __half* __restrict__ Vh = g_vh + (size_t)bh*SEQ*HDIM;

    // --- stage Q (separate region)
    const u32 qbase = sbase + 2*STGB;
#pragma unroll
    for (int i = 0; i < 8; ++i) {
        int c = tid + i*256;                 // 0..2047
        int mat = c >> 10, rem = c & 1023, row = rem >> 3, cc = rem & 7;
        const __half* s = (mat ? Ql : Qh) + (size_t)row*HDIM + cc*8;
        CP_ASYNC16(qbase + mat*QMATB + row*KVROWB + cc*16,
                   (u64)__cvta_generic_to_global(s));
    }
    CP_COMMIT();

    auto load_kv = [&](int stg, int kt) {
        const u32 sb = sbase + stg*STGB;
#pragma unroll
        for (int i = 0; i < 6; ++i) {
            int c = tid + i*256;             // 0..1535 over Kh,Kl,Vh
            int mat = c >> 9, rem = c & 511, row = rem >> 3, cc = rem & 7;
            const __half* s =
                ((mat == 0) ? Kh : (mat == 1) ? Kl : Vh)
                + (size_t)(kt*64 + row)*HDIM + cc*8;
            CP_ASYNC16(sb + mat*MATKB + row*KVROWB + cc*16,
                       (u64)__cvta_generic_to_global(s));
        }
        CP_COMMIT();
    };
    load_kv(0, 0);
    if (tid < 64) Ms[0][tid] = mask[b*SEQ + tid];

    CP_WAIT1();                  // Q done (KV0 may be in flight)
    __syncthreads();

    // --- extract Q fragments
    u32 qfh[4][4], qfl[4][4];
#pragma unroll
    for (int ks = 0; ks < 4; ++ks) {
        u32 ra = qbase + (u32)((wid*16 + (lane & 15))*KVROWB
                               + (ks*16 + ((lane >> 4) & 1)*8)*2);
        LDSM4(qfh[ks][0], qfh[ks][1], qfh[ks][2], qfh[ks][3], ra);
        LDSM4(qfl[ks][0], qfl[ks][1], qfl[ks][2], qfl[ks][3], ra + QMATB);
    }

    float O[8][4];
#pragma unroll
    for (int dt = 0; dt < 8; ++dt)
#pragma unroll
        for (int r = 0; r < 4; ++r) O[dt][r] = 0.f;
    float m0v = -1e30f, m1v = -1e30f, l0v = 0.f, l1v = 0.f;

    for (int kt = 0; kt < NKT; ++kt) {
        const int stg = kt & 1;
        if (kt + 1 < NKT) {
            load_kv(stg ^ 1, kt + 1);
            if (tid < 64) Ms[(kt+1) & 1][tid] = mask[b*SEQ + (kt+1)*64 + tid];
            CP_WAIT1();
        } else {
            CP_WAIT0();
        }
        __syncthreads();

        const u32 kb = sbase + stg*STGB;

        // ---- S = Q K^T (3-term) ----
        float S[8][4];
#pragma unroll
        for (int nt = 0; nt < 8; ++nt)
#pragma unroll
            for (int r = 0; r < 4; ++r) S[nt][r] = 0.f;

#pragma unroll
        for (int ks = 0; ks < 4; ++ks) {
            u32 kfh[4][4], kfl[4][4];
#pragma unroll
            for (int g = 0; g < 4; ++g) {
                u32 rb = kb + (u32)((g*16 + (lane & 15))*KVROWB
                                    + (ks*16 + ((lane >> 4) & 1)*8)*2);
                LDSM4(kfh[g][0], kfh[g][1], kfh[g][2], kfh[g][3], rb);
                LDSM4(kfl[g][0], kfl[g][1], kfl[g][2], kfl[g][3], rb + MATKB);
            }
#pragma unroll
            for (int nt = 0; nt < 8; ++nt) {
                const int g = nt >> 1, o = nt & 1;
                MMA_F16(S[nt], qfh[ks], kfh[g][o], kfh[g][o+2]);
                MMA_F16(S[nt], qfh[ks], kfl[g][o], kfl[g][o+2]);
                MMA_F16(S[nt], qfl[ks], kfh[g][o], kfh[g][o+2]);
            }
        }

        // ---- mask ----
        const int c0 = (lane & 3) * 2;
#pragma unroll
        for (int nt = 0; nt < 8; ++nt) {
            if (Ms[stg][nt*8 + c0]     == 0) { S[nt][0] = -1e30f; S[nt][2] = -1e30f; }
            if (Ms[stg][nt*8 + c0 + 1] == 0) { S[nt][1] = -1e30f; S[nt][3] = -1e30f; }
        }

        // ---- online softmax (base-2) ----
        float mx0 = -1e30f, mx1 = -1e30f;
#pragma unroll
        for (int nt = 0; nt < 8; ++nt) {
            mx0 = fmaxf(mx0, fmaxf(S[nt][0], S[nt][1]));
            mx1 = fmaxf(mx1, fmaxf(S[nt][2], S[nt][3]));
        }
#pragma unroll
        for (int off = 1; off < 4; off <<= 1) {
            mx0 = fmaxf(mx0, __shfl_xor_sync(0xffffffffu, mx0, off));
            mx1 = fmaxf(mx1, __shfl_xor_sync(0xffffffffu, mx1, off));
        }
        const float mn0 = fmaxf(m0v, mx0), mn1 = fmaxf(m1v, mx1);
        const float cr0 = exp2_fast(m0v - mn0), cr1 = exp2_fast(m1v - mn1);
        m0v = mn0; m1v = mn1;

        float s0 = 0.f, s1 = 0.f;
        u32 pa[4][4], pl[4][4];
#pragma unroll
        for (int t = 0; t < 4; ++t) {
#pragma unroll
            for (int hf = 0; hf < 2; ++hf) {
                const int nt = 2*t + hf;
                float p0 = exp2_fast(S[nt][0] - mn0);
                float p1 = exp2_fast(S[nt][1] - mn0);
                float p2 = exp2_fast(S[nt][2] - mn1);
                float p3 = exp2_fast(S[nt][3] - mn1);
                s0 += p0 + p1; s1 += p2 + p3;
                float h0 = __half2float(__float2half_rn(p0));
                float h1 = __half2float(__float2half_rn(p1));
                float h2 = __half2float(__float2half_rn(p2));
                float h3 = __half2float(__float2half_rn(p3));
                pa[t][2*hf]     = pack_h16(h0, h1);
                pa[t][2*hf + 1] = pack_h16(h2, h3);
                pl[t][2*hf]     = pack_h16(p0 - h0, p1 - h1);
                pl[t][2*hf + 1] = pack_h16(p2 - h2, p3 - h3);
            }
        }
#pragma unroll
        for (int off = 1; off < 4; off <<= 1) {
            s0 += __shfl_xor_sync(0xffffffffu, s0, off);
            s1 += __shfl_xor_sync(0xffffffffu, s1, off);
        }
        l0v = l0v*cr0 + s0;
        l1v = l1v*cr1 + s1;
#pragma unroll
        for (int dt = 0; dt < 8; ++dt) {
            O[dt][0] *= cr0; O[dt][1] *= cr0;
            O[dt][2] *= cr1; O[dt][3] *= cr1;
        }

        // ---- O += P V (2-term, V single) ----
        const u32 vb = kb + 2*MATKB;
#pragma unroll
        for (int t = 0; t < 4; ++t) {
            u32 vfh[4][4];
#pragma unroll
            for (int dg = 0; dg < 4; ++dg) {
                u32 rb = vb + (u32)((t*16 + (lane & 15))*KVROWB
                                    + (dg*16 + ((lane >> 4) & 1)*8)*2);
                LDSM4T(vfh[dg][0], vfh[dg][1], vfh[dg][2], vfh[dg][3], rb);
            }
#pragma unroll
            for (int dt = 0; dt < 8; ++dt) {
                const int g = dt >> 1, o = (dt & 1) * 2;
                MMA_F16(O[dt], pa[t], vfh[g][o], vfh[g][o+1]);
                MMA_F16(O[dt], pl[t], vfh[g][o], vfh[g][o+1]);
            }
        }
        __syncthreads();
    }

    // ---- epilogue: normalize, write ctx single fp16 [m, h*64+d] ----
    const float i0 = 1.f / l0v, i1 = 1.f / l1v;
    const int r = lane >> 2;
    const size_t row0 = (size_t)b*SEQ + q0 + wid*16 + r;
#pragma unroll
    for (int dt = 0; dt < 8; ++dt) {
        const int col = h*HDIM + dt*8 + (lane & 3)*2;
        *(u32*)&g_a[row0*DIMS + col]     = pack_h16(O[dt][0]*i0, O[dt][1]*i0);
        *(u32*)&g_a[(row0+8)*DIMS + col] = pack_h16(O[dt][2]*i1, O[dt][3]*i1);
    }
}

// ---------------------------------------------------------------------------
extern "C" void kernel_launch(void* const* d_in, const int* in_sizes, int n_in,
                              void* d_out, int out_size)
{
    const float* input = (const float*)d_in[0];
    const int*   mask  = (const int*)d_in[1];
    const float* wq = (const float*)d_in[2];
    const float* bq = (const float*)d_in[3];
    const float* wk = (const float*)d_in[4];
    const float* bk = (const float*)d_in[5];
    const float* wv = (const float*)d_in[6];
    const float* bv = (const float*)d_in[7];
    const float* wo = (const float*)d_in[8];
    const float* bo = (const float*)d_in[9];
    float* out = (float*)d_out;
    (void)in_sizes; (void)n_in; (void)out_size;

    const int nx4 = MROWS * DIMS / 4;
    const int nw4 = DIMS * DIMS / 4;

    cvt_single<<<(nx4 + 255)/256, 256>>>(input, nx4);
    cvt_split<<<(nw4 + 255)/256, 256>>>(wq, 0ull,                nw4);
    cvt_split<<<(nw4 + 255)/256, 256>>>(wk, (size_t)DIMS*DIMS,   nw4);
    cvt_split<<<(nw4 + 255)/256, 256>>>(wv, (size_t)DIMS*DIMS*2, nw4);
    cvt_split<<<(nw4 + 255)/256, 256>>>(wo, (size_t)DIMS*DIMS*3, nw4);

    cudaFuncSetAttribute(gemm_kernel<0>, cudaFuncAttributeMaxDynamicSharedMemorySize, GEMM_DSMEM);
    cudaFuncSetAttribute(gemm_kernel<1>, cudaFuncAttributeMaxDynamicSharedMemorySize, GEMM_DSMEM);
    cudaFuncSetAttribute(gemm_kernel<2>, cudaFuncAttributeMaxDynamicSharedMemorySize, GEMM_DSMEM);
    cudaFuncSetAttribute(gemm_kernel<3>, cudaFuncAttributeMaxDynamicSharedMemorySize, GEMM_DSMEM);

    dim3 ggrid(DIMS/128, MROWS/256);   // 8 x 32 = 256 CTAs

    // q pre-scaled by (1/8)*log2(e) for base-2 softmax
    gemm_kernel<0><<<ggrid, 256, GEMM_DSMEM>>>(0, bq, nullptr, 0.125f * 1.44269504f);
    gemm_kernel<1><<<ggrid, 256, GEMM_DSMEM>>>(1, bk, nullptr, 1.0f);
    gemm_kernel<2><<<ggrid, 256, GEMM_DSMEM>>>(2, bv, nullptr, 1.0f);

    cudaFuncSetAttribute(attn_kernel, cudaFuncAttributeMaxDynamicSharedMemorySize, ATTN_DSMEM);
    attn_kernel<<<dim3(SEQ/128, BATCH*NHEAD), 256, ATTN_DSMEM>>>(mask);

    gemm_kernel<3><<<ggrid, 256, GEMM_DSMEM>>>(3, bo, out, 1.0f);
}

// round 7
// speedup vs baseline: 4.7670x; 1.5905x over previous
#include <cuda_runtime.h>
#include <cuda.h>
#include <cuda_fp16.h>
#include <cstdint>

#define BATCH 4
#define SEQ   2048
#define DIMS  1024
#define NHEAD 16
#define HDIM  64
#define MROWS (BATCH*SEQ)

typedef unsigned int u32;
typedef unsigned long long u64;

// ---------------- scratch (static device allocations, TMA-aligned) ----------------
__device__ __align__(1024) __half g_a [(size_t)MROWS*DIMS];   // input / ctx, single fp16
__device__ __align__(1024) __half g_wh[4ull*DIMS*DIMS];       // weights hi (wq,wk single here)
__device__ __align__(1024) __half g_wl[4ull*DIMS*DIMS];       // weights lo (wv,wo only)
__device__ __align__(1024) __half g_q [(size_t)MROWS*DIMS];   // Q single [b,h,s,d]
__device__ __align__(1024) __half g_kh[(size_t)MROWS*DIMS];   // K split
__device__ __align__(1024) __half g_kl[(size_t)MROWS*DIMS];
__device__ __align__(1024) __half g_v [(size_t)MROWS*DIMS];   // V single

// ---------------- device helpers ----------------
__device__ __forceinline__ u32 smem_u32(const void* p) {
    u32 a;
    asm("{ .reg .u64 t; cvta.to.shared.u64 t, %1; cvt.u32.u64 %0, t; }" : "=r"(a) : "l"(p));
    return a;
}
#define SW128(o) ((o) ^ (((o) >> 3) & 0x70))

#define MBARRIER_INIT(mb, cnt) \
    asm volatile("mbarrier.init.shared.b64 [%0], %1;" :: "r"((u32)(mb)), "r"((u32)(cnt)) : "memory")
#define MBARRIER_EXPECT_TX(mb, bytes) \
    asm volatile("mbarrier.arrive.expect_tx.shared.b64 _, [%0], %1;" \
                 :: "r"((u32)(mb)), "r"((u32)(bytes)) : "memory")
#define MBARRIER_WAIT_PARITY(mb, par) do { \
    u32 _m = (u32)(mb); u32 _p = (u32)(par); u32 _done; \
    asm volatile("{\n\t.reg .pred p;\n\t" \
        "mbarrier.try_wait.parity.acquire.cta.shared::cta.b64 p, [%1], %2;\n\t" \
        "selp.b32 %0, 1, 0, p;\n\t}" : "=r"(_done) : "r"(_m), "r"(_p) : "memory"); \
    if (!_done) { \
        asm volatile("{\n\t.reg .pred P1;\n\t" \
            "WL_%=:\n\t" \
            "mbarrier.try_wait.parity.acquire.cta.shared::cta.b64 P1, [%0], %1, 0x989680;\n\t" \
            "@P1 bra.uni WD_%=;\n\t" \
            "bra.uni WL_%=;\n\t" \
            "WD_%=:\n\t}" :: "r"(_m), "r"(_p) : "memory"); \
    } } while (0)

#define TMA_LOAD_2D(dst, map, x, y, mbar) \
    asm volatile("cp.async.bulk.tensor.2d.shared::cta.global.tile.mbarrier::complete_tx::bytes " \
                 "[%0], [%1, {%2, %3}], [%4];" \
                 :: "r"((u32)(dst)), "l"(map), "r"((int)(x)), "r"((int)(y)), "r"((u32)(mbar)) \
                 : "memory")

#define LDSM4(r0, r1, r2, r3, a) \
    asm volatile("ldmatrix.sync.aligned.m8n8.x4.shared.b16 {%0,%1,%2,%3}, [%4];" \
                 : "=r"(r0), "=r"(r1), "=r"(r2), "=r"(r3) : "r"(a))
#define LDSM4T(r0, r1, r2, r3, a) \
    asm volatile("ldmatrix.sync.aligned.m8n8.x4.trans.shared.b16 {%0,%1,%2,%3}, [%4];" \
                 : "=r"(r0), "=r"(r1), "=r"(r2), "=r"(r3) : "r"(a))
#define MMA_F16(d, a, b0, b1) \
    asm volatile("mma.sync.aligned.m16n8k16.row.col.f32.f16.f16.f32 " \
                 "{%0,%1,%2,%3}, {%4,%5,%6,%7}, {%8,%9}, {%0,%1,%2,%3};" \
                 : "+f"((d)[0]), "+f"((d)[1]), "+f"((d)[2]), "+f"((d)[3]) \
                 : "r"((a)[0]), "r"((a)[1]), "r"((a)[2]), "r"((a)[3]), \
                   "r"(b0), "r"(b1))

__device__ __forceinline__ u32 pack_h16(float a, float b) {
    __half2 t = __floats2half2_rn(a, b);
    return *(u32*)&t;
}
__device__ __forceinline__ float exp2_fast(float t) {
    t = fmaxf(t, -126.0f);
    float r = t + 12582912.0f;
    int   i = __float_as_int(r) << 23;
    float f = t - (r - 12582912.0f);
    float p = fmaf(f, 0.00961813f, 0.05550411f);
    p = fmaf(f, p, 0.24022651f);
    p = fmaf(f, p, 0.69314718f);
    p = fmaf(f, p, 1.0f);
    return __int_as_float(__float_as_int(p) + i);
}

// ---------------- conversions ----------------
__global__ void cvt_single(const float* __restrict__ src, __half* __restrict__ dst, int n4)
{
    int i = blockIdx.x * 256 + threadIdx.x;
    if (i >= n4) return;
    float4 v = ((const float4*)src)[i];
    ((u32*)dst)[i*2+0] = pack_h16(v.x, v.y);
    ((u32*)dst)[i*2+1] = pack_h16(v.z, v.w);
}
__global__ void cvt_split(const float* __restrict__ src,
                          __half* __restrict__ H, __half* __restrict__ L, int n4)
{
    int i = blockIdx.x * 256 + threadIdx.x;
    if (i >= n4) return;
    float4 v = ((const float4*)src)[i];
    float h0 = __half2float(__float2half_rn(v.x));
    float h1 = __half2float(__float2half_rn(v.y));
    float h2 = __half2float(__float2half_rn(v.z));
    float h3 = __half2float(__float2half_rn(v.w));
    ((u32*)H)[i*2+0] = pack_h16(h0, h1);
    ((u32*)H)[i*2+1] = pack_h16(h2, h3);
    ((u32*)L)[i*2+0] = pack_h16(v.x - h0, v.y - h1);
    ((u32*)L)[i*2+1] = pack_h16(v.z - h2, v.w - h3);
}

// ---------------- TMA fp16 GEMM ----------------
// C[m0:+256, n0:+128] = scale*(A @ W^T + bias). TERMS=2: W = Wh + Wl.
#define ASTG   32768                 // 256 x 128B
#define BSTG   16384                 // 128 x 128B
#define STAGEB (ASTG + 2*BSTG)       // 65536
#define GEMM_DSMEM (2*STAGEB + 1024)

template<int OUT_SEL, int TERMS>   // OUT_SEL: 0=Q single 1=K split 2=V single 3=fp32
__global__ __launch_bounds__(256, 1) void gemm_kernel(
    int widx, const float* __restrict__ bias, float* __restrict__ outp, float scale,
    const __grid_constant__ CUtensorMap mA,
    const __grid_constant__ CUtensorMap mBh,
    const __grid_constant__ CUtensorMap mBl)
{
    extern __shared__ char dyn[];
    __shared__ float s_bias[128];
    __shared__ __align__(8) u64 s_bar[2];

    const int tid = threadIdx.x, wid = tid >> 5, lane = tid & 31;
    const int m0 = blockIdx.y * 256, n0 = blockIdx.x * 128;
    const int wrow = widx * DIMS + n0;
    const int wm = (wid >> 1) * 64, wn = (wid & 1) * 64;
    const u32 sb0 = (smem_u32(dyn) + 1023u) & ~1023u;
    const u32 bar0 = smem_u32(&s_bar[0]);
    const u32 TXB = (TERMS == 2) ? (ASTG + 2*BSTG) : (ASTG + BSTG);

    if (tid < 128) s_bias[tid] = bias[n0 + tid];
    if (tid == 0) { MBARRIER_INIT(bar0, 1); MBARRIER_INIT(bar0 + 8, 1); }
    __syncthreads();

    if (tid == 0) {
        MBARRIER_EXPECT_TX(bar0, TXB);
        TMA_LOAD_2D(sb0,             &mA,  0, m0,   bar0);
        TMA_LOAD_2D(sb0 + ASTG,      &mBh, 0, wrow, bar0);
        if (TERMS == 2) TMA_LOAD_2D(sb0 + ASTG + BSTG, &mBl, 0, wrow, bar0);
    }

    float acc[4][8][4];
#pragma unroll
    for (int i = 0; i < 4; ++i)
#pragma unroll
        for (int j = 0; j < 8; ++j)
#pragma unroll
            for (int r = 0; r < 4; ++r) acc[i][j][r] = 0.f;

    const int lrow = lane & 15;
    const int lk16 = ((lane >> 4) & 1) * 16;   // byte offset within 32B k-step

    for (int it = 0; it < 16; ++it) {
        if (tid == 0 && it + 1 < 16) {
            const u32 sb = sb0 + ((it+1) & 1) * STAGEB;
            const u32 mb = bar0 + ((it+1) & 1) * 8;
            MBARRIER_EXPECT_TX(mb, TXB);
            TMA_LOAD_2D(sb,             &mA,  (it+1)*64, m0,   mb);
            TMA_LOAD_2D(sb + ASTG,      &mBh, (it+1)*64, wrow, mb);
            if (TERMS == 2) TMA_LOAD_2D(sb + ASTG + BSTG, &mBl, (it+1)*64, wrow, mb);
        }
        MBARRIER_WAIT_PARITY(bar0 + (it & 1)*8, (it >> 1) & 1);
        const u32 st = sb0 + (it & 1) * STAGEB;

#pragma unroll
        for (int ks = 0; ks < 4; ++ks) {
            u32 a[4][4], bh[4][4], bl[4][4];
#pragma unroll
            for (int ti = 0; ti < 4; ++ti) {
                u32 off = (u32)((wm + ti*16 + lrow)*128 + ks*32 + lk16);
                LDSM4(a[ti][0], a[ti][1], a[ti][2], a[ti][3], st + SW128(off));
            }
#pragma unroll
            for (int g = 0; g < 4; ++g) {
                u32 off = (u32)((wn + g*16 + lrow)*128 + ks*32 + lk16);
                LDSM4(bh[g][0], bh[g][1], bh[g][2], bh[g][3], st + ASTG + SW128(off));
                if (TERMS == 2)
                    LDSM4(bl[g][0], bl[g][1], bl[g][2], bl[g][3], st + ASTG + BSTG + SW128(off));
            }
#pragma unroll
            for (int ti = 0; ti < 4; ++ti) {
#pragma unroll
                for (int nj = 0; nj < 8; ++nj) {
                    const int g = nj >> 1, o = nj & 1;
                    MMA_F16(acc[ti][nj], a[ti], bh[g][o], bh[g][o+2]);
                    if (TERMS == 2) MMA_F16(acc[ti][nj], a[ti], bl[g][o], bl[g][o+2]);
                }
            }
        }
        __syncthreads();
    }

#pragma unroll
    for (int ti = 0; ti < 4; ++ti) {
#pragma unroll
        for (int nj = 0; nj < 8; ++nj) {
            const int col = wn + nj*8 + (lane & 3)*2;
            const int r0  = m0 + wm + ti*16 + (lane >> 2);
            const float b0 = s_bias[col], b1 = s_bias[col + 1];
            float v0 = (acc[ti][nj][0] + b0) * scale;
            float v1 = (acc[ti][nj][1] + b1) * scale;
            float v2 = (acc[ti][nj][2] + b0) * scale;
            float v3 = (acc[ti][nj][3] + b1) * scale;
            if (OUT_SEL <= 2) {
                const int nglob = n0 + col;
                const int hh = nglob >> 6, dd = nglob & 63;
                const int bb = r0 >> 11, ss = r0 & 2047;
                const size_t base = (((size_t)bb*NHEAD + hh)*SEQ + ss)*HDIM + dd;
                if (OUT_SEL == 0) {
                    *(u32*)&g_q[base]          = pack_h16(v0, v1);
                    *(u32*)&g_q[base + 8*HDIM] = pack_h16(v2, v3);
                } else if (OUT_SEL == 2) {
                    *(u32*)&g_v[base]          = pack_h16(v0, v1);
                    *(u32*)&g_v[base + 8*HDIM] = pack_h16(v2, v3);
                } else {
                    float h0 = __half2float(__float2half_rn(v0));
                    float h1 = __half2float(__float2half_rn(v1));
                    float h2 = __half2float(__float2half_rn(v2));
                    float h3 = __half2float(__float2half_rn(v3));
                    *(u32*)&g_kh[base]          = pack_h16(h0, h1);
                    *(u32*)&g_kl[base]          = pack_h16(v0 - h0, v1 - h1);
                    *(u32*)&g_kh[base + 8*HDIM] = pack_h16(h2, h3);
                    *(u32*)&g_kl[base + 8*HDIM] = pack_h16(v2 - h2, v3 - h3);
                }
            } else {
                *(float2*)&outp[(size_t)r0 * DIMS + n0 + col]     = make_float2(v0, v1);
                *(float2*)&outp[(size_t)(r0+8) * DIMS + n0 + col] = make_float2(v2, v3);
            }
        }
    }
}

// ---------------- TMA flash attention ----------------
// S = Q (Kh + Kl)  (2-term);  O += P V (1-term, P and V single fp16).
#define NKT   (SEQ/64)
#define KSTG  8192                  // 64 x 128B
#define ASTGB (3*KSTG)              // Kh, Kl, V
#define QB    16384                 // 128 x 128B
#define ATTN_DSMEM (2*ASTGB + QB + 1024)

__global__ __launch_bounds__(256, 1) void attn_kernel(
    const int* __restrict__ mask,
    const __grid_constant__ CUtensorMap mQ,
    const __grid_constant__ CUtensorMap mKh,
    const __grid_constant__ CUtensorMap mKl,
    const __grid_constant__ CUtensorMap mV)
{
    extern __shared__ char dyn[];
    __shared__ int Ms[2][64];
    __shared__ __align__(8) u64 s_bar[3];

    const int tid = threadIdx.x, wid = tid >> 5, lane = tid & 31;
    const int bh = blockIdx.y, b = bh >> 4, h = bh & 15;
    const int q0 = blockIdx.x * 128;
    const int krow0 = bh * SEQ;
    const u32 sb0 = (smem_u32(dyn) + 1023u) & ~1023u;
    const u32 qb  = sb0 + 2*ASTGB;
    const u32 bar0 = smem_u32(&s_bar[0]);

    if (tid == 0) {
        MBARRIER_INIT(bar0, 1); MBARRIER_INIT(bar0 + 8, 1); MBARRIER_INIT(bar0 + 16, 1);
    }
    __syncthreads();

    if (tid == 0) {
        MBARRIER_EXPECT_TX(bar0 + 16, QB);
        TMA_LOAD_2D(qb, &mQ, 0, krow0 + q0, bar0 + 16);
        MBARRIER_EXPECT_TX(bar0, ASTGB);
        TMA_LOAD_2D(sb0,          &mKh, 0, krow0, bar0);
        TMA_LOAD_2D(sb0 + KSTG,   &mKl, 0, krow0, bar0);
        TMA_LOAD_2D(sb0 + 2*KSTG, &mV,  0, krow0, bar0);
    }
    if (tid < 64) Ms[0][tid] = mask[b*SEQ + tid];

    const int lrow = lane & 15;
    const int lk16 = ((lane >> 4) & 1) * 16;

    MBARRIER_WAIT_PARITY(bar0 + 16, 0);
    u32 qf[4][4];
#pragma unroll
    for (int ks = 0; ks < 4; ++ks) {
        u32 off = (u32)((wid*16 + lrow)*128 + ks*32 + lk16);
        LDSM4(qf[ks][0], qf[ks][1], qf[ks][2], qf[ks][3], qb + SW128(off));
    }
    __syncthreads();

    float O[8][4];
#pragma unroll
    for (int dt = 0; dt < 8; ++dt)
#pragma unroll
        for (int r = 0; r < 4; ++r) O[dt][r] = 0.f;
    float m0v = -1e30f, m1v = -1e30f, l0v = 0.f, l1v = 0.f;

    for (int kt = 0; kt < NKT; ++kt) {
        const int stg = kt & 1;
        if (tid == 0 && kt + 1 < NKT) {
            const u32 sb = sb0 + ((kt+1) & 1) * ASTGB;
            const u32 mb = bar0 + ((kt+1) & 1) * 8;
            MBARRIER_EXPECT_TX(mb, ASTGB);
            TMA_LOAD_2D(sb,          &mKh, 0, krow0 + (kt+1)*64, mb);
            TMA_LOAD_2D(sb + KSTG,   &mKl, 0, krow0 + (kt+1)*64, mb);
            TMA_LOAD_2D(sb + 2*KSTG, &mV,  0, krow0 + (kt+1)*64, mb);
        }
        if (tid < 64 && kt + 1 < NKT) Ms[(kt+1) & 1][tid] = mask[b*SEQ + (kt+1)*64 + tid];
        MBARRIER_WAIT_PARITY(bar0 + stg*8, (kt >> 1) & 1);
        const u32 kb = sb0 + stg * ASTGB;

        // ---- S = Q K^T (2-term) ----
        float S[8][4];
#pragma unroll
        for (int nt = 0; nt < 8; ++nt)
#pragma unroll
            for (int r = 0; r < 4; ++r) S[nt][r] = 0.f;

#pragma unroll
        for (int ks = 0; ks < 4; ++ks) {
            u32 kfh[4][4], kfl[4][4];
#pragma unroll
            for (int g = 0; g < 4; ++g) {
                u32 off = (u32)((g*16 + lrow)*128 + ks*32 + lk16);
                LDSM4(kfh[g][0], kfh[g][1], kfh[g][2], kfh[g][3], kb + SW128(off));
                LDSM4(kfl[g][0], kfl[g][1], kfl[g][2], kfl[g][3], kb + KSTG + SW128(off));
            }
#pragma unroll
            for (int nt = 0; nt < 8; ++nt) {
                const int g = nt >> 1, o = nt & 1;
                MMA_F16(S[nt], qf[ks], kfh[g][o], kfh[g][o+2]);
                MMA_F16(S[nt], qf[ks], kfl[g][o], kfl[g][o+2]);
            }
        }

        // ---- mask ----
        const int c0 = (lane & 3) * 2;
#pragma unroll
        for (int nt = 0; nt < 8; ++nt) {
            if (Ms[stg][nt*8 + c0]     == 0) { S[nt][0] = -1e30f; S[nt][2] = -1e30f; }
            if (Ms[stg][nt*8 + c0 + 1] == 0) { S[nt][1] = -1e30f; S[nt][3] = -1e30f; }
        }

        // ---- online softmax (base-2) ----
        float mx0 = -1e30f, mx1 = -1e30f;
#pragma unroll
        for (int nt = 0; nt < 8; ++nt) {
            mx0 = fmaxf(mx0, fmaxf(S[nt][0], S[nt][1]));
            mx1 = fmaxf(mx1, fmaxf(S[nt][2], S[nt][3]));
        }
#pragma unroll
        for (int off = 1; off < 4; off <<= 1) {
            mx0 = fmaxf(mx0, __shfl_xor_sync(0xffffffffu, mx0, off));
            mx1 = fmaxf(mx1, __shfl_xor_sync(0xffffffffu, mx1, off));
        }
        const float mn0 = fmaxf(m0v, mx0), mn1 = fmaxf(m1v, mx1);
        const float cr0 = exp2_fast(m0v - mn0), cr1 = exp2_fast(m1v - mn1);
        m0v = mn0; m1v = mn1;

        float s0 = 0.f, s1 = 0.f;
        u32 pa[4][4];
#pragma unroll
        for (int t = 0; t < 4; ++t) {
#pragma unroll
            for (int hf = 0; hf < 2; ++hf) {
                const int nt = 2*t + hf;
                float p0 = exp2_fast(S[nt][0] - mn0);
                float p1 = exp2_fast(S[nt][1] - mn0);
                float p2 = exp2_fast(S[nt][2] - mn1);
                float p3 = exp2_fast(S[nt][3] - mn1);
                s0 += p0 + p1; s1 += p2 + p3;
                pa[t][2*hf]     = pack_h16(p0, p1);
                pa[t][2*hf + 1] = pack_h16(p2, p3);
            }
        }
#pragma unroll
        for (int off = 1; off < 4; off <<= 1) {
            s0 += __shfl_xor_sync(0xffffffffu, s0, off);
            s1 += __shfl_xor_sync(0xffffffffu, s1, off);
        }
        l0v = l0v*cr0 + s0;
        l1v = l1v*cr1 + s1;
#pragma unroll
        for (int dt = 0; dt < 8; ++dt) {
            O[dt][0] *= cr0; O[dt][1] *= cr0;
            O[dt][2] *= cr1; O[dt][3] *= cr1;
        }

        // ---- O += P V (1-term) ----
#pragma unroll
        for (int t = 0; t < 4; ++t) {
            u32 vf[4][4];
#pragma unroll
            for (int dg = 0; dg < 4; ++dg) {
                u32 off = (u32)((t*16 + lrow)*128 + dg*32 + lk16);
                LDSM4T(vf[dg][0], vf[dg][1], vf[dg][2], vf[dg][3], kb + 2*KSTG + SW128(off));
            }
#pragma unroll
            for (int dt = 0; dt < 8; ++dt) {
                const int g = dt >> 1, o = (dt & 1) * 2;
                MMA_F16(O[dt], pa[t], vf[g][o], vf[g][o+1]);
            }
        }
        __syncthreads();
    }

    // ---- epilogue: normalize, write ctx single fp16 [m, h*64+d] ----
    const float i0 = 1.f / l0v, i1 = 1.f / l1v;
    const int r = lane >> 2;
    const size_t row0 = (size_t)b*SEQ + q0 + wid*16 + r;
#pragma unroll
    for (int dt = 0; dt < 8; ++dt) {
        const int col = h*HDIM + dt*8 + (lane & 3)*2;
        *(u32*)&g_a[row0*DIMS + col]     = pack_h16(O[dt][0]*i0, O[dt][1]*i0);
        *(u32*)&g_a[(row0+8)*DIMS + col] = pack_h16(O[dt][2]*i1, O[dt][3]*i1);
    }
}

// ---------------- host: tensor map plumbing ----------------
typedef CUresult (*PFN_encode)(CUtensorMap*, CUtensorMapDataType, cuuint32_t, void*,
                               const cuuint64_t*, const cuuint64_t*, const cuuint32_t*,
                               const cuuint32_t*, CUtensorMapInterleave, CUtensorMapSwizzle,
                               CUtensorMapL2promotion, CUtensorMapFloatOOBfill);

static PFN_encode get_encoder() {
    static PFN_encode fn = nullptr;
    if (!fn) {
        cudaDriverEntryPointQueryResult st;
#if CUDART_VERSION >= 12050
        cudaGetDriverEntryPointByVersion("cuTensorMapEncodeTiled", (void**)&fn, 12000,
                                         cudaEnableDefault, &st);
#else
        cudaGetDriverEntryPoint("cuTensorMapEncodeTiled", (void**)&fn, cudaEnableDefault, &st);
#endif
    }
    return fn;
}

static void build_map(PFN_encode enc, CUtensorMap* m, void* ptr,
                      unsigned long long rows, unsigned long long cols,
                      unsigned bx, unsigned by) {
    cuuint64_t dims[2]    = {cols, rows};
    cuuint64_t strides[1] = {cols * 2};
    cuuint32_t box[2]     = {bx, by};
    cuuint32_t es[2]      = {1, 1};
    enc(m, CU_TENSOR_MAP_DATA_TYPE_FLOAT16, 2, ptr, dims, strides, box, es,
        CU_TENSOR_MAP_INTERLEAVE_NONE, CU_TENSOR_MAP_SWIZZLE_128B,
        CU_TENSOR_MAP_L2_PROMOTION_L2_128B, CU_TENSOR_MAP_FLOAT_OOB_FILL_NONE);
}

extern "C" void kernel_launch(void* const* d_in, const int* in_sizes, int n_in,
                              void* d_out, int out_size)
{
    const float* input = (const float*)d_in[0];
    const int*   mask  = (const int*)d_in[1];
    const float* wq = (const float*)d_in[2];
    const float* bq = (const float*)d_in[3];
    const float* wk = (const float*)d_in[4];
    const float* bk = (const float*)d_in[5];
    const float* wv = (const float*)d_in[6];
    const float* bv = (const float*)d_in[7];
    const float* wo = (const float*)d_in[8];
    const float* bo = (const float*)d_in[9];
    float* out = (float*)d_out;
    (void)in_sizes; (void)n_in; (void)out_size;

    PFN_encode enc = get_encoder();
    void *pa, *pwh, *pwl, *pq, *pkh, *pkl, *pv;
    cudaGetSymbolAddress(&pa,  g_a);
    cudaGetSymbolAddress(&pwh, g_wh);
    cudaGetSymbolAddress(&pwl, g_wl);
    cudaGetSymbolAddress(&pq,  g_q);
    cudaGetSymbolAddress(&pkh, g_kh);
    cudaGetSymbolAddress(&pkl, g_kl);
    cudaGetSymbolAddress(&pv,  g_v);

    static CUtensorMap mA, mWh, mWl, mQ, mKh, mKl, mV;
    const unsigned long long HR = (unsigned long long)BATCH * NHEAD * SEQ;
    build_map(enc, &mA,  pa,  MROWS,   DIMS, 64, 256);
    build_map(enc, &mWh, pwh, 4*DIMS,  DIMS, 64, 128);
    build_map(enc, &mWl, pwl, 4*DIMS,  DIMS, 64, 128);
    build_map(enc, &mQ,  pq,  HR, HDIM, 64, 128);
    build_map(enc, &mKh, pkh, HR, HDIM, 64, 64);
    build_map(enc, &mKl, pkl, HR, HDIM, 64, 64);
    build_map(enc, &mV,  pv,  HR, HDIM, 64, 64);

    const int nx4 = MROWS * DIMS / 4;
    const int nw4 = DIMS * DIMS / 4;
    const size_t DD = (size_t)DIMS * DIMS;
    __half* wh = (__half*)pwh;
    __half* wl = (__half*)pwl;

    cvt_single<<<(nx4 + 255)/256, 256>>>(input, (__half*)pa, nx4);
    cvt_single<<<(nw4 + 255)/256, 256>>>(wq, wh,        nw4);   // WQ single
    cvt_single<<<(nw4 + 255)/256, 256>>>(wk, wh + DD,   nw4);   // WK single
    cvt_split <<<(nw4 + 255)/256, 256>>>(wv, wh + 2*DD, wl + 2*DD, nw4);
    cvt_split <<<(nw4 + 255)/256, 256>>>(wo, wh + 3*DD, wl + 3*DD, nw4);

    cudaFuncSetAttribute(gemm_kernel<0,1>, cudaFuncAttributeMaxDynamicSharedMemorySize, GEMM_DSMEM);
    cudaFuncSetAttribute(gemm_kernel<1,1>, cudaFuncAttributeMaxDynamicSharedMemorySize, GEMM_DSMEM);
    cudaFuncSetAttribute(gemm_kernel<2,2>, cudaFuncAttributeMaxDynamicSharedMemorySize, GEMM_DSMEM);
    cudaFuncSetAttribute(gemm_kernel<3,2>, cudaFuncAttributeMaxDynamicSharedMemorySize, GEMM_DSMEM);
    cudaFuncSetAttribute(attn_kernel,      cudaFuncAttributeMaxDynamicSharedMemorySize, ATTN_DSMEM);

    dim3 ggrid(DIMS/128, MROWS/256);   // 8 x 32

    gemm_kernel<0,1><<<ggrid, 256, GEMM_DSMEM>>>(0, bq, nullptr, 0.125f*1.44269504f, mA, mWh, mWl);
    gemm_kernel<1,1><<<ggrid, 256, GEMM_DSMEM>>>(1, bk, nullptr, 1.0f, mA, mWh, mWl);
    gemm_kernel<2,2><<<ggrid, 256, GEMM_DSMEM>>>(2, bv, nullptr, 1.0f, mA, mWh, mWl);

    attn_kernel<<<dim3(SEQ/128, BATCH*NHEAD), 256, ATTN_DSMEM>>>(mask, mQ, mKh, mKl, mV);

    gemm_kernel<3,2><<<ggrid, 256, GEMM_DSMEM>>>(3, bo, out, 1.0f, mA, mWh, mWl);
}

// round 8
// speedup vs baseline: 6.2396x; 1.3089x over previous
#include <cuda_runtime.h>
#include <cuda.h>
#include <cuda_fp16.h>
#include <cstdint>

#define BATCH 4
#define SEQ   2048
#define DIMS  1024
#define NHEAD 16
#define HDIM  64
#define MROWS (BATCH*SEQ)

typedef unsigned int u32;
typedef unsigned long long u64;

// ---------------- scratch (static device allocations, TMA-aligned) ----------------
__device__ __align__(1024) __half g_a[(size_t)MROWS*DIMS];    // input / ctx, fp16
__device__ __align__(1024) __half g_w[4ull*DIMS*DIMS];        // wq,wk,wv,wo fp16
__device__ __align__(1024) __half g_q[(size_t)MROWS*DIMS];    // [b,h,s,d]
__device__ __align__(1024) __half g_k[(size_t)MROWS*DIMS];
__device__ __align__(1024) __half g_v[(size_t)MROWS*DIMS];

// ---------------- device helpers ----------------
__device__ __forceinline__ u32 smem_u32(const void* p) {
    u32 a;
    asm("{ .reg .u64 t; cvta.to.shared.u64 t, %1; cvt.u32.u64 %0, t; }" : "=r"(a) : "l"(p));
    return a;
}
#define SW128(o) ((o) ^ (((o) >> 3) & 0x70))

#define MBARRIER_INIT(mb, cnt) \
    asm volatile("mbarrier.init.shared.b64 [%0], %1;" :: "r"((u32)(mb)), "r"((u32)(cnt)) : "memory")
#define MBARRIER_EXPECT_TX(mb, bytes) \
    asm volatile("mbarrier.arrive.expect_tx.shared.b64 _, [%0], %1;" \
                 :: "r"((u32)(mb)), "r"((u32)(bytes)) : "memory")
#define MBARRIER_WAIT_PARITY(mb, par) do { \
    u32 _m = (u32)(mb); u32 _p = (u32)(par); u32 _done; \
    asm volatile("{\n\t.reg .pred p;\n\t" \
        "mbarrier.try_wait.parity.acquire.cta.shared::cta.b64 p, [%1], %2;\n\t" \
        "selp.b32 %0, 1, 0, p;\n\t}" : "=r"(_done) : "r"(_m), "r"(_p) : "memory"); \
    if (!_done) { \
        asm volatile("{\n\t.reg .pred P1;\n\t" \
            "WL_%=:\n\t" \
            "mbarrier.try_wait.parity.acquire.cta.shared::cta.b64 P1, [%0], %1, 0x989680;\n\t" \
            "@P1 bra.uni WD_%=;\n\t" \
            "bra.uni WL_%=;\n\t" \
            "WD_%=:\n\t}" :: "r"(_m), "r"(_p) : "memory"); \
    } } while (0)

#define TMA_LOAD_2D(dst, map, x, y, mbar) \
    asm volatile("cp.async.bulk.tensor.2d.shared::cta.global.tile.mbarrier::complete_tx::bytes " \
                 "[%0], [%1, {%2, %3}], [%4];" \
                 :: "r"((u32)(dst)), "l"(map), "r"((int)(x)), "r"((int)(y)), "r"((u32)(mbar)) \
                 : "memory")

#define LDSM4(r0, r1, r2, r3, a) \
    asm volatile("ldmatrix.sync.aligned.m8n8.x4.shared.b16 {%0,%1,%2,%3}, [%4];" \
                 : "=r"(r0), "=r"(r1), "=r"(r2), "=r"(r3) : "r"(a))
#define LDSM4T(r0, r1, r2, r3, a) \
    asm volatile("ldmatrix.sync.aligned.m8n8.x4.trans.shared.b16 {%0,%1,%2,%3}, [%4];" \
                 : "=r"(r0), "=r"(r1), "=r"(r2), "=r"(r3) : "r"(a))
#define MMA_F16(d, a, b0, b1) \
    asm volatile("mma.sync.aligned.m16n8k16.row.col.f32.f16.f16.f32 " \
                 "{%0,%1,%2,%3}, {%4,%5,%6,%7}, {%8,%9}, {%0,%1,%2,%3};" \
                 : "+f"((d)[0]), "+f"((d)[1]), "+f"((d)[2]), "+f"((d)[3]) \
                 : "r"((a)[0]), "r"((a)[1]), "r"((a)[2]), "r"((a)[3]), \
                   "r"(b0), "r"(b1))

__device__ __forceinline__ u32 pack_h16(float a, float b) {
    __half2 t = __floats2half2_rn(a, b);
    return *(u32*)&t;
}
__device__ __forceinline__ float exp2_fast(float t) {
    t = fmaxf(t, -126.0f);
    float r = t + 12582912.0f;
    int   i = __float_as_int(r) << 23;
    float f = t - (r - 12582912.0f);
    float p = fmaf(f, 0.00961813f, 0.05550411f);
    p = fmaf(f, p, 0.24022651f);
    p = fmaf(f, p, 0.69314718f);
    p = fmaf(f, p, 1.0f);
    return __int_as_float(__float_as_int(p) + i);
}

// ---------------- conversion ----------------
__global__ void cvt_single(const float* __restrict__ src, __half* __restrict__ dst, int n4)
{
    int i = blockIdx.x * 256 + threadIdx.x;
    if (i >= n4) return;
    float4 v = ((const float4*)src)[i];
    ((u32*)dst)[i*2+0] = pack_h16(v.x, v.y);
    ((u32*)dst)[i*2+1] = pack_h16(v.z, v.w);
}

// ---------------- TMA fp16 GEMM (single-term) ----------------
// C[m0:+256, n0:+128] = scale*(A @ W^T + bias)
// FUSED=1: blockIdx.z in {0,1,2} selects wq/wk/wv and g_q/g_k/g_v output.
// FUSED=0: widx=3 (wo), fp32 output to outp.
#define ASTG   32768                 // 256 x 128B
#define BSTG   16384                 // 128 x 128B
#define STAGEB (ASTG + BSTG)         // 49152
#define GEMM_DSMEM (2*STAGEB + 1024)

template<int FUSED>
__global__ __launch_bounds__(256, 1) void gemm_kernel(
    const float* __restrict__ bq, const float* __restrict__ bk,
    const float* __restrict__ bv, float* __restrict__ outp,
    const __grid_constant__ CUtensorMap mA,
    const __grid_constant__ CUtensorMap mW)
{
    extern __shared__ char dyn[];
    __shared__ float s_bias[128];
    __shared__ __align__(8) u64 s_bar[2];

    const int tid = threadIdx.x, wid = tid >> 5, lane = tid & 31;
    const int z = FUSED ? blockIdx.z : 3;
    const int m0 = blockIdx.y * 256, n0 = blockIdx.x * 128;
    const int wrow = z * DIMS + n0;
    const int wm = (wid >> 1) * 64, wn = (wid & 1) * 64;
    const u32 sb0 = (smem_u32(dyn) + 1023u) & ~1023u;
    const u32 bar0 = smem_u32(&s_bar[0]);
    const float scale = (FUSED && z == 0) ? 0.125f * 1.44269504f : 1.0f;

    if (tid < 128) {
        const float* bp = FUSED ? (z == 0 ? bq : z == 1 ? bk : bv) : bq;
        s_bias[tid] = bp[n0 + tid];
    }
    if (tid == 0) { MBARRIER_INIT(bar0, 1); MBARRIER_INIT(bar0 + 8, 1); }
    __syncthreads();

    if (tid == 0) {
        MBARRIER_EXPECT_TX(bar0, STAGEB);
        TMA_LOAD_2D(sb0,        &mA, 0, m0,   bar0);
        TMA_LOAD_2D(sb0 + ASTG, &mW, 0, wrow, bar0);
    }

    float acc[4][8][4];
#pragma unroll
    for (int i = 0; i < 4; ++i)
#pragma unroll
        for (int j = 0; j < 8; ++j)
#pragma unroll
            for (int r = 0; r < 4; ++r) acc[i][j][r] = 0.f;

    const int lrow = lane & 15;
    const int lk16 = ((lane >> 4) & 1) * 16;

    for (int it = 0; it < 16; ++it) {
        if (tid == 0 && it + 1 < 16) {
            const u32 sb = sb0 + ((it+1) & 1) * STAGEB;
            const u32 mb = bar0 + ((it+1) & 1) * 8;
            MBARRIER_EXPECT_TX(mb, STAGEB);
            TMA_LOAD_2D(sb,        &mA, (it+1)*64, m0,   mb);
            TMA_LOAD_2D(sb + ASTG, &mW, (it+1)*64, wrow, mb);
        }
        MBARRIER_WAIT_PARITY(bar0 + (it & 1)*8, (it >> 1) & 1);
        const u32 st = sb0 + (it & 1) * STAGEB;

#pragma unroll
        for (int ks = 0; ks < 4; ++ks) {
            u32 a[4][4], bw[4][4];
#pragma unroll
            for (int ti = 0; ti < 4; ++ti) {
                u32 off = (u32)((wm + ti*16 + lrow)*128 + ks*32 + lk16);
                LDSM4(a[ti][0], a[ti][1], a[ti][2], a[ti][3], st + SW128(off));
            }
#pragma unroll
            for (int g = 0; g < 4; ++g) {
                u32 off = (u32)((wn + g*16 + lrow)*128 + ks*32 + lk16);
                LDSM4(bw[g][0], bw[g][1], bw[g][2], bw[g][3], st + ASTG + SW128(off));
            }
#pragma unroll
            for (int ti = 0; ti < 4; ++ti) {
#pragma unroll
                for (int nj = 0; nj < 8; ++nj) {
                    const int g = nj >> 1, o = nj & 1;
                    MMA_F16(acc[ti][nj], a[ti], bw[g][o], bw[g][o+2]);
                }
            }
        }
        __syncthreads();
    }

#pragma unroll
    for (int ti = 0; ti < 4; ++ti) {
#pragma unroll
        for (int nj = 0; nj < 8; ++nj) {
            const int col = wn + nj*8 + (lane & 3)*2;
            const int r0  = m0 + wm + ti*16 + (lane >> 2);
            const float b0 = s_bias[col], b1 = s_bias[col + 1];
            float v0 = (acc[ti][nj][0] + b0) * scale;
            float v1 = (acc[ti][nj][1] + b1) * scale;
            float v2 = (acc[ti][nj][2] + b0) * scale;
            float v3 = (acc[ti][nj][3] + b1) * scale;
            if (FUSED) {
                __half* dst = (z == 0) ? g_q : (z == 1) ? g_k : g_v;
                const int nglob = n0 + col;
                const int hh = nglob >> 6, dd = nglob & 63;
                const int bb = r0 >> 11, ss = r0 & 2047;
                const size_t base = (((size_t)bb*NHEAD + hh)*SEQ + ss)*HDIM + dd;
                *(u32*)&dst[base]          = pack_h16(v0, v1);
                *(u32*)&dst[base + 8*HDIM] = pack_h16(v2, v3);
            } else {
                *(float2*)&outp[(size_t)r0 * DIMS + n0 + col]     = make_float2(v0, v1);
                *(float2*)&outp[(size_t)(r0+8) * DIMS + n0 + col] = make_float2(v2, v3);
            }
        }
    }
}

// ---------------- TMA flash attention (all single fp16) ----------------
// S = Q K^T (1 term);  O += P V (1 term).
#define NKT   (SEQ/64)
#define KSTG  8192                  // 64 x 128B
#define ASTGB (2*KSTG)              // K, V
#define QB    16384                 // 128 x 128B
#define ATTN_DSMEM (2*ASTGB + QB + 1024)

__global__ __launch_bounds__(256, 1) void attn_kernel(
    const int* __restrict__ mask,
    const __grid_constant__ CUtensorMap mQ,
    const __grid_constant__ CUtensorMap mK,
    const __grid_constant__ CUtensorMap mV)
{
    extern __shared__ char dyn[];
    __shared__ int Ms[2][64];
    __shared__ __align__(8) u64 s_bar[3];

    const int tid = threadIdx.x, wid = tid >> 5, lane = tid & 31;
    const int bh = blockIdx.y, b = bh >> 4;
    const int q0 = blockIdx.x * 128;
    const int krow0 = bh * SEQ;
    const u32 sb0 = (smem_u32(dyn) + 1023u) & ~1023u;
    const u32 qb  = sb0 + 2*ASTGB;
    const u32 bar0 = smem_u32(&s_bar[0]);

    if (tid == 0) {
        MBARRIER_INIT(bar0, 1); MBARRIER_INIT(bar0 + 8, 1); MBARRIER_INIT(bar0 + 16, 1);
    }
    __syncthreads();

    if (tid == 0) {
        MBARRIER_EXPECT_TX(bar0 + 16, QB);
        TMA_LOAD_2D(qb, &mQ, 0, krow0 + q0, bar0 + 16);
        MBARRIER_EXPECT_TX(bar0, ASTGB);
        TMA_LOAD_2D(sb0,        &mK, 0, krow0, bar0);
        TMA_LOAD_2D(sb0 + KSTG, &mV, 0, krow0, bar0);
    }
    if (tid < 64) Ms[0][tid] = mask[b*SEQ + tid];

    const int lrow = lane & 15;
    const int lk16 = ((lane >> 4) & 1) * 16;

    MBARRIER_WAIT_PARITY(bar0 + 16, 0);
    u32 qf[4][4];
#pragma unroll
    for (int ks = 0; ks < 4; ++ks) {
        u32 off = (u32)((wid*16 + lrow)*128 + ks*32 + lk16);
        LDSM4(qf[ks][0], qf[ks][1], qf[ks][2], qf[ks][3], qb + SW128(off));
    }
    __syncthreads();

    float O[8][4];
#pragma unroll
    for (int dt = 0; dt < 8; ++dt)
#pragma unroll
        for (int r = 0; r < 4; ++r) O[dt][r] = 0.f;
    float m0v = -1e30f, m1v = -1e30f, l0v = 0.f, l1v = 0.f;

    for (int kt = 0; kt < NKT; ++kt) {
        const int stg = kt & 1;
        if (tid == 0 && kt + 1 < NKT) {
            const u32 sb = sb0 + ((kt+1) & 1) * ASTGB;
            const u32 mb = bar0 + ((kt+1) & 1) * 8;
            MBARRIER_EXPECT_TX(mb, ASTGB);
            TMA_LOAD_2D(sb,        &mK, 0, krow0 + (kt+1)*64, mb);
            TMA_LOAD_2D(sb + KSTG, &mV, 0, krow0 + (kt+1)*64, mb);
        }
        if (tid < 64 && kt + 1 < NKT) Ms[(kt+1) & 1][tid] = mask[b*SEQ + (kt+1)*64 + tid];
        MBARRIER_WAIT_PARITY(bar0 + stg*8, (kt >> 1) & 1);
        const u32 kb = sb0 + stg * ASTGB;

        // ---- S = Q K^T (1 term) ----
        float S[8][4];
#pragma unroll
        for (int nt = 0; nt < 8; ++nt)
#pragma unroll
            for (int r = 0; r < 4; ++r) S[nt][r] = 0.f;

#pragma unroll
        for (int ks = 0; ks < 4; ++ks) {
            u32 kf[4][4];
#pragma unroll
            for (int g = 0; g < 4; ++g) {
                u32 off = (u32)((g*16 + lrow)*128 + ks*32 + lk16);
                LDSM4(kf[g][0], kf[g][1], kf[g][2], kf[g][3], kb + SW128(off));
            }
#pragma unroll
            for (int nt = 0; nt < 8; ++nt) {
                const int g = nt >> 1, o = nt & 1;
                MMA_F16(S[nt], qf[ks], kf[g][o], kf[g][o+2]);
            }
        }

        // ---- mask ----
        const int c0 = (lane & 3) * 2;
#pragma unroll
        for (int nt = 0; nt < 8; ++nt) {
            if (Ms[stg][nt*8 + c0]     == 0) { S[nt][0] = -1e30f; S[nt][2] = -1e30f; }
            if (Ms[stg][nt*8 + c0 + 1] == 0) { S[nt][1] = -1e30f; S[nt][3] = -1e30f; }
        }

        // ---- online softmax (base-2) ----
        float mx0 = -1e30f, mx1 = -1e30f;
#pragma unroll
        for (int nt = 0; nt < 8; ++nt) {
            mx0 = fmaxf(mx0, fmaxf(S[nt][0], S[nt][1]));
            mx1 = fmaxf(mx1, fmaxf(S[nt][2], S[nt][3]));
        }
#pragma unroll
        for (int off = 1; off < 4; off <<= 1) {
            mx0 = fmaxf(mx0, __shfl_xor_sync(0xffffffffu, mx0, off));
            mx1 = fmaxf(mx1, __shfl_xor_sync(0xffffffffu, mx1, off));
        }
        const float mn0 = fmaxf(m0v, mx0), mn1 = fmaxf(m1v, mx1);
        const float cr0 = exp2_fast(m0v - mn0), cr1 = exp2_fast(m1v - mn1);
        m0v = mn0; m1v = mn1;

        float s0 = 0.f, s1 = 0.f;
        u32 pa[4][4];
#pragma unroll
        for (int t = 0; t < 4; ++t) {
#pragma unroll
            for (int hf = 0; hf < 2; ++hf) {
                const int nt = 2*t + hf;
                float p0 = exp2_fast(S[nt][0] - mn0);
                float p1 = exp2_fast(S[nt][1] - mn0);
                float p2 = exp2_fast(S[nt][2] - mn1);
                float p3 = exp2_fast(S[nt][3] - mn1);
                s0 += p0 + p1; s1 += p2 + p3;
                pa[t][2*hf]     = pack_h16(p0, p1);
                pa[t][2*hf + 1] = pack_h16(p2, p3);
            }
        }
#pragma unroll
        for (int off = 1; off < 4; off <<= 1) {
            s0 += __shfl_xor_sync(0xffffffffu, s0, off);
            s1 += __shfl_xor_sync(0xffffffffu, s1, off);
        }
        l0v = l0v*cr0 + s0;
        l1v = l1v*cr1 + s1;
#pragma unroll
        for (int dt = 0; dt < 8; ++dt) {
            O[dt][0] *= cr0; O[dt][1] *= cr0;
            O[dt][2] *= cr1; O[dt][3] *= cr1;
        }

        // ---- O += P V (1 term) ----
#pragma unroll
        for (int t = 0; t < 4; ++t) {
            u32 vf[4][4];
#pragma unroll
            for (int dg = 0; dg < 4; ++dg) {
                u32 off = (u32)((t*16 + lrow)*128 + dg*32 + lk16);
                LDSM4T(vf[dg][0], vf[dg][1], vf[dg][2], vf[dg][3], kb + KSTG + SW128(off));
            }
#pragma unroll
            for (int dt = 0; dt < 8; ++dt) {
                const int g = dt >> 1, o = (dt & 1) * 2;
                MMA_F16(O[dt], pa[t], vf[g][o], vf[g][o+1]);
            }
        }
        __syncthreads();
    }

    // ---- epilogue: normalize, write ctx fp16 [m, h*64+d] ----
    const int h = bh & 15;
    const float i0 = 1.f / l0v, i1 = 1.f / l1v;
    const int r = lane >> 2;
    const size_t row0 = (size_t)b*SEQ + q0 + wid*16 + r;
#pragma unroll
    for (int dt = 0; dt < 8; ++dt) {
        const int col = h*HDIM + dt*8 + (lane & 3)*2;
        *(u32*)&g_a[row0*DIMS + col]     = pack_h16(O[dt][0]*i0, O[dt][1]*i0);
        *(u32*)&g_a[(row0+8)*DIMS + col] = pack_h16(O[dt][2]*i1, O[dt][3]*i1);
    }
}

// ---------------- host: tensor map plumbing ----------------
typedef CUresult (*PFN_encode)(CUtensorMap*, CUtensorMapDataType, cuuint32_t, void*,
                               const cuuint64_t*, const cuuint64_t*, const cuuint32_t*,
                               const cuuint32_t*, CUtensorMapInterleave, CUtensorMapSwizzle,
                               CUtensorMapL2promotion, CUtensorMapFloatOOBfill);

static PFN_encode get_encoder() {
    static PFN_encode fn = nullptr;
    if (!fn) {
        cudaDriverEntryPointQueryResult st;
#if CUDART_VERSION >= 12050
        cudaGetDriverEntryPointByVersion("cuTensorMapEncodeTiled", (void**)&fn, 12000,
                                         cudaEnableDefault, &st);
#else
        cudaGetDriverEntryPoint("cuTensorMapEncodeTiled", (void**)&fn, cudaEnableDefault, &st);
#endif
    }
    return fn;
}

static void build_map(PFN_encode enc, CUtensorMap* m, void* ptr,
                      unsigned long long rows, unsigned long long cols,
                      unsigned bx, unsigned by) {
    cuuint64_t dims[2]    = {cols, rows};
    cuuint64_t strides[1] = {cols * 2};
    cuuint32_t box[2]     = {bx, by};
    cuuint32_t es[2]      = {1, 1};
    enc(m, CU_TENSOR_MAP_DATA_TYPE_FLOAT16, 2, ptr, dims, strides, box, es,
        CU_TENSOR_MAP_INTERLEAVE_NONE, CU_TENSOR_MAP_SWIZZLE_128B,
        CU_TENSOR_MAP_L2_PROMOTION_L2_128B, CU_TENSOR_MAP_FLOAT_OOB_FILL_NONE);
}

extern "C" void kernel_launch(void* const* d_in, const int* in_sizes, int n_in,
                              void* d_out, int out_size)
{
    const float* input = (const float*)d_in[0];
    const int*   mask  = (const int*)d_in[1];
    const float* wq = (const float*)d_in[2];
    const float* bq = (const float*)d_in[3];
    const float* wk = (const float*)d_in[4];
    const float* bk = (const float*)d_in[5];
    const float* wv = (const float*)d_in[6];
    const float* bv = (const float*)d_in[7];
    const float* wo = (const float*)d_in[8];
    const float* bo = (const float*)d_in[9];
    float* out = (float*)d_out;
    (void)in_sizes; (void)n_in; (void)out_size;

    PFN_encode enc = get_encoder();
    void *pa, *pw, *pq, *pk, *pv;
    cudaGetSymbolAddress(&pa, g_a);
    cudaGetSymbolAddress(&pw, g_w);
    cudaGetSymbolAddress(&pq, g_q);
    cudaGetSymbolAddress(&pk, g_k);
    cudaGetSymbolAddress(&pv, g_v);

    static CUtensorMap mA, mW, mQ, mK, mV;
    const unsigned long long HR = (unsigned long long)BATCH * NHEAD * SEQ;
    build_map(enc, &mA, pa, MROWS,  DIMS, 64, 256);
    build_map(enc, &mW, pw, 4*DIMS, DIMS, 64, 128);
    build_map(enc, &mQ, pq, HR, HDIM, 64, 128);
    build_map(enc, &mK, pk, HR, HDIM, 64, 64);
    build_map(enc, &mV, pv, HR, HDIM, 64, 64);

    const int nx4 = MROWS * DIMS / 4;
    const int nw4 = DIMS * DIMS / 4;
    const size_t DD = (size_t)DIMS * DIMS;
    __half* w = (__half*)pw;

    cvt_single<<<(nx4 + 255)/256, 256>>>(input, (__half*)pa, nx4);
    cvt_single<<<(nw4 + 255)/256, 256>>>(wq, w,        nw4);
    cvt_single<<<(nw4 + 255)/256, 256>>>(wk, w + DD,   nw4);
    cvt_single<<<(nw4 + 255)/256, 256>>>(wv, w + 2*DD, nw4);
    cvt_single<<<(nw4 + 255)/256, 256>>>(wo, w + 3*DD, nw4);

    cudaFuncSetAttribute(gemm_kernel<1>, cudaFuncAttributeMaxDynamicSharedMemorySize, GEMM_DSMEM);
    cudaFuncSetAttribute(gemm_kernel<0>, cudaFuncAttributeMaxDynamicSharedMemorySize, GEMM_DSMEM);
    cudaFuncSetAttribute(attn_kernel,    cudaFuncAttributeMaxDynamicSharedMemorySize, ATTN_DSMEM);

    // fused Q/K/V projections (z selects weight + destination)
    gemm_kernel<1><<<dim3(DIMS/128, MROWS/256, 3), 256, GEMM_DSMEM>>>(
        bq, bk, bv, nullptr, mA, mW);

    attn_kernel<<<dim3(SEQ/128, BATCH*NHEAD), 256, ATTN_DSMEM>>>(mask, mQ, mK, mV);

    // output projection (wo), fp32 out
    gemm_kernel<0><<<dim3(DIMS/128, MROWS/256, 1), 256, GEMM_DSMEM>>>(
        bo, nullptr, nullptr, out, mA, mW);
}

// round 9
// speedup vs baseline: 6.6180x; 1.0607x over previous
#include <cuda_runtime.h>
#include <cuda.h>
#include <cuda_fp16.h>
#include <cstdint>

#define BATCH 4
#define SEQ   2048
#define DIMS  1024
#define NHEAD 16
#define HDIM  64
#define MROWS (BATCH*SEQ)

typedef unsigned int u32;
typedef unsigned long long u64;

// ---------------- scratch (static device allocations, TMA-aligned) ----------------
__device__ __align__(1024) __half g_a[(size_t)MROWS*DIMS];    // input / ctx, fp16
__device__ __align__(1024) __half g_w[4ull*DIMS*DIMS];        // wq,wk,wv,wo fp16
__device__ __align__(1024) __half g_q[(size_t)MROWS*DIMS];    // [b,h,s,d]
__device__ __align__(1024) __half g_k[(size_t)MROWS*DIMS];
__device__ __align__(1024) __half g_v[(size_t)MROWS*DIMS];

// ---------------- device helpers ----------------
__device__ __forceinline__ u32 smem_u32(const void* p) {
    u32 a;
    asm("{ .reg .u64 t; cvta.to.shared.u64 t, %1; cvt.u32.u64 %0, t; }" : "=r"(a) : "l"(p));
    return a;
}
#define SW128(o) ((o) ^ (((o) >> 3) & 0x70))

#define MBARRIER_INIT(mb, cnt) \
    asm volatile("mbarrier.init.shared.b64 [%0], %1;" :: "r"((u32)(mb)), "r"((u32)(cnt)) : "memory")
#define MBARRIER_EXPECT_TX(mb, bytes) \
    asm volatile("mbarrier.arrive.expect_tx.shared.b64 _, [%0], %1;" \
                 :: "r"((u32)(mb)), "r"((u32)(bytes)) : "memory")
#define MBARRIER_WAIT_PARITY(mb, par) do { \
    u32 _m = (u32)(mb); u32 _p = (u32)(par); u32 _done; \
    asm volatile("{\n\t.reg .pred p;\n\t" \
        "mbarrier.try_wait.parity.acquire.cta.shared::cta.b64 p, [%1], %2;\n\t" \
        "selp.b32 %0, 1, 0, p;\n\t}" : "=r"(_done) : "r"(_m), "r"(_p) : "memory"); \
    if (!_done) { \
        asm volatile("{\n\t.reg .pred P1;\n\t" \
            "WL_%=:\n\t" \
            "mbarrier.try_wait.parity.acquire.cta.shared::cta.b64 P1, [%0], %1, 0x989680;\n\t" \
            "@P1 bra.uni WD_%=;\n\t" \
            "bra.uni WL_%=;\n\t" \
            "WD_%=:\n\t}" :: "r"(_m), "r"(_p) : "memory"); \
    } } while (0)

#define TMA_LOAD_2D(dst, map, x, y, mbar) \
    asm volatile("cp.async.bulk.tensor.2d.shared::cta.global.tile.mbarrier::complete_tx::bytes " \
                 "[%0], [%1, {%2, %3}], [%4];" \
                 :: "r"((u32)(dst)), "l"(map), "r"((int)(x)), "r"((int)(y)), "r"((u32)(mbar)) \
                 : "memory")

#define LDSM4(r0, r1, r2, r3, a) \
    asm volatile("ldmatrix.sync.aligned.m8n8.x4.shared.b16 {%0,%1,%2,%3}, [%4];" \
                 : "=r"(r0), "=r"(r1), "=r"(r2), "=r"(r3) : "r"(a))
#define LDSM4T(r0, r1, r2, r3, a) \
    asm volatile("ldmatrix.sync.aligned.m8n8.x4.trans.shared.b16 {%0,%1,%2,%3}, [%4];" \
                 : "=r"(r0), "=r"(r1), "=r"(r2), "=r"(r3) : "r"(a))
#define MMA_F16(d, a, b0, b1) \
    asm volatile("mma.sync.aligned.m16n8k16.row.col.f32.f16.f16.f32 " \
                 "{%0,%1,%2,%3}, {%4,%5,%6,%7}, {%8,%9}, {%0,%1,%2,%3};" \
                 : "+f"((d)[0]), "+f"((d)[1]), "+f"((d)[2]), "+f"((d)[3]) \
                 : "r"((a)[0]), "r"((a)[1]), "r"((a)[2]), "r"((a)[3]), \
                   "r"(b0), "r"(b1))

__device__ __forceinline__ u32 pack_h16(float a, float b) {
    __half2 t = __floats2half2_rn(a, b);
    return *(u32*)&t;
}
__device__ __forceinline__ float exp2_fast(float t) {
    t = fmaxf(t, -126.0f);
    float r = t + 12582912.0f;
    int   i = __float_as_int(r) << 23;
    float f = t - (r - 12582912.0f);
    float p = fmaf(f, 0.00961813f, 0.05550411f);
    p = fmaf(f, p, 0.24022651f);
    p = fmaf(f, p, 0.69314718f);
    p = fmaf(f, p, 1.0f);
    return __int_as_float(__float_as_int(p) + i);
}

// ---------------- fused conversion: input + 4 weights in one launch ----------------
// segment 0: input (NX4 float4s) -> g_a; segments 1..4: weights -> g_w + (s-1)*DD
#define NX4 (MROWS*DIMS/4)
#define NW4 (DIMS*DIMS/4)
__global__ void cvt_all(const float* __restrict__ input,
                        const float* __restrict__ wq, const float* __restrict__ wk,
                        const float* __restrict__ wv, const float* __restrict__ wo)
{
    int i = blockIdx.x * 256 + threadIdx.x;
    const float* src;
    u32* dst;
    if (i < NX4) {
        src = input; dst = (u32*)g_a;
    } else {
        int j = i - NX4;
        int seg = j / NW4;
        i = j - seg * NW4;
        src = (seg == 0) ? wq : (seg == 1) ? wk : (seg == 2) ? wv : wo;
        dst = (u32*)(g_w + (size_t)seg * DIMS * DIMS);
    }
    float4 v = ((const float4*)src)[i];
    dst[i*2+0] = pack_h16(v.x, v.y);
    dst[i*2+1] = pack_h16(v.z, v.w);
}

// ---------------- TMA fp16 GEMM (single-term) ----------------
// C[m0:+256, n0:+128] = scale*(A @ W^T + bias)
// FUSED=1: blockIdx.z in {0,1,2} selects wq/wk/wv and g_q/g_k/g_v output.
// FUSED=0: widx=3 (wo), fp32 output to outp.
#define ASTG   32768                 // 256 x 128B
#define BSTG   16384                 // 128 x 128B
#define STAGEB (ASTG + BSTG)         // 49152
#define GEMM_DSMEM (2*STAGEB + 1024)

template<int FUSED>
__global__ __launch_bounds__(256, 1) void gemm_kernel(
    const float* __restrict__ bq, const float* __restrict__ bk,
    const float* __restrict__ bv, float* __restrict__ outp,
    const __grid_constant__ CUtensorMap mA,
    const __grid_constant__ CUtensorMap mW)
{
    extern __shared__ char dyn[];
    __shared__ float s_bias[128];
    __shared__ __align__(8) u64 s_bar[2];

    const int tid = threadIdx.x, wid = tid >> 5, lane = tid & 31;
    const int z = FUSED ? blockIdx.z : 3;
    const int m0 = blockIdx.y * 256, n0 = blockIdx.x * 128;
    const int wrow = z * DIMS + n0;
    const int wm = (wid >> 1) * 64, wn = (wid & 1) * 64;
    const u32 sb0 = (smem_u32(dyn) + 1023u) & ~1023u;
    const u32 bar0 = smem_u32(&s_bar[0]);
    const float scale = (FUSED && z == 0) ? 0.125f * 1.44269504f : 1.0f;

    if (tid < 128) {
        const float* bp = FUSED ? (z == 0 ? bq : z == 1 ? bk : bv) : bq;
        s_bias[tid] = bp[n0 + tid];
    }
    if (tid == 0) { MBARRIER_INIT(bar0, 1); MBARRIER_INIT(bar0 + 8, 1); }
    __syncthreads();

    if (tid == 0) {
        MBARRIER_EXPECT_TX(bar0, STAGEB);
        TMA_LOAD_2D(sb0,        &mA, 0, m0,   bar0);
        TMA_LOAD_2D(sb0 + ASTG, &mW, 0, wrow, bar0);
    }

    float acc[4][8][4];
#pragma unroll
    for (int i = 0; i < 4; ++i)
#pragma unroll
        for (int j = 0; j < 8; ++j)
#pragma unroll
            for (int r = 0; r < 4; ++r) acc[i][j][r] = 0.f;

    const int lrow = lane & 15;
    const int lk16 = ((lane >> 4) & 1) * 16;

    for (int it = 0; it < 16; ++it) {
        if (tid == 0 && it + 1 < 16) {
            const u32 sb = sb0 + ((it+1) & 1) * STAGEB;
            const u32 mb = bar0 + ((it+1) & 1) * 8;
            MBARRIER_EXPECT_TX(mb, STAGEB);
            TMA_LOAD_2D(sb,        &mA, (it+1)*64, m0,   mb);
            TMA_LOAD_2D(sb + ASTG, &mW, (it+1)*64, wrow, mb);
        }
        MBARRIER_WAIT_PARITY(bar0 + (it & 1)*8, (it >> 1) & 1);
        const u32 st = sb0 + (it & 1) * STAGEB;

#pragma unroll
        for (int ks = 0; ks < 4; ++ks) {
            u32 a[4][4], bw[4][4];
#pragma unroll
            for (int ti = 0; ti < 4; ++ti) {
                u32 off = (u32)((wm + ti*16 + lrow)*128 + ks*32 + lk16);
                LDSM4(a[ti][0], a[ti][1], a[ti][2], a[ti][3], st + SW128(off));
            }
#pragma unroll
            for (int g = 0; g < 4; ++g) {
                u32 off = (u32)((wn + g*16 + lrow)*128 + ks*32 + lk16);
                LDSM4(bw[g][0], bw[g][1], bw[g][2], bw[g][3], st + ASTG + SW128(off));
            }
#pragma unroll
            for (int ti = 0; ti < 4; ++ti) {
#pragma unroll
                for (int nj = 0; nj < 8; ++nj) {
                    const int g = nj >> 1, o = nj & 1;
                    MMA_F16(acc[ti][nj], a[ti], bw[g][o], bw[g][o+2]);
                }
            }
        }
        __syncthreads();
    }

#pragma unroll
    for (int ti = 0; ti < 4; ++ti) {
#pragma unroll
        for (int nj = 0; nj < 8; ++nj) {
            const int col = wn + nj*8 + (lane & 3)*2;
            const int r0  = m0 + wm + ti*16 + (lane >> 2);
            const float b0 = s_bias[col], b1 = s_bias[col + 1];
            float v0 = (acc[ti][nj][0] + b0) * scale;
            float v1 = (acc[ti][nj][1] + b1) * scale;
            float v2 = (acc[ti][nj][2] + b0) * scale;
            float v3 = (acc[ti][nj][3] + b1) * scale;
            if (FUSED) {
                __half* dst = (z == 0) ? g_q : (z == 1) ? g_k : g_v;
                const int nglob = n0 + col;
                const int hh = nglob >> 6, dd = nglob & 63;
                const int bb = r0 >> 11, ss = r0 & 2047;
                const size_t base = (((size_t)bb*NHEAD + hh)*SEQ + ss)*HDIM + dd;
                *(u32*)&dst[base]          = pack_h16(v0, v1);
                *(u32*)&dst[base + 8*HDIM] = pack_h16(v2, v3);
            } else {
                *(float2*)&outp[(size_t)r0 * DIMS + n0 + col]     = make_float2(v0, v1);
                *(float2*)&outp[(size_t)(r0+8) * DIMS + n0 + col] = make_float2(v2, v3);
            }
        }
    }
}

// ---------------- TMA flash attention (single fp16, 2 CTAs/SM) ----------------
#define NKT   (SEQ/64)
#define KSTG  8192                  // 64 x 128B
#define ASTGB (2*KSTG)              // K, V
#define QB    16384                 // 128 x 128B
#define ATTN_DSMEM (2*ASTGB + QB + 1024)

__global__ __launch_bounds__(256, 2) void attn_kernel(
    const int* __restrict__ mask,
    const __grid_constant__ CUtensorMap mQ,
    const __grid_constant__ CUtensorMap mK,
    const __grid_constant__ CUtensorMap mV)
{
    extern __shared__ char dyn[];
    __shared__ int Ms[2][64];
    __shared__ __align__(8) u64 s_bar[3];

    const int tid = threadIdx.x, wid = tid >> 5, lane = tid & 31;
    const int bh = blockIdx.y, b = bh >> 4;
    const int q0 = blockIdx.x * 128;
    const int krow0 = bh * SEQ;
    const u32 sb0 = (smem_u32(dyn) + 1023u) & ~1023u;
    const u32 qb  = sb0 + 2*ASTGB;
    const u32 bar0 = smem_u32(&s_bar[0]);

    if (tid == 0) {
        MBARRIER_INIT(bar0, 1); MBARRIER_INIT(bar0 + 8, 1); MBARRIER_INIT(bar0 + 16, 1);
    }
    __syncthreads();

    if (tid == 0) {
        MBARRIER_EXPECT_TX(bar0 + 16, QB);
        TMA_LOAD_2D(qb, &mQ, 0, krow0 + q0, bar0 + 16);
        MBARRIER_EXPECT_TX(bar0, ASTGB);
        TMA_LOAD_2D(sb0,        &mK, 0, krow0, bar0);
        TMA_LOAD_2D(sb0 + KSTG, &mV, 0, krow0, bar0);
    }
    if (tid < 64) Ms[0][tid] = mask[b*SEQ + tid];

    const int lrow = lane & 15;
    const int lk16 = ((lane >> 4) & 1) * 16;

    MBARRIER_WAIT_PARITY(bar0 + 16, 0);
    u32 qf[4][4];
#pragma unroll
    for (int ks = 0; ks < 4; ++ks) {
        u32 off = (u32)((wid*16 + lrow)*128 + ks*32 + lk16);
        LDSM4(qf[ks][0], qf[ks][1], qf[ks][2], qf[ks][3], qb + SW128(off));
    }
    __syncthreads();

    float O[8][4];
#pragma unroll
    for (int dt = 0; dt < 8; ++dt)
#pragma unroll
        for (int r = 0; r < 4; ++r) O[dt][r] = 0.f;
    float m0v = -1e30f, m1v = -1e30f, l0v = 0.f, l1v = 0.f;

    for (int kt = 0; kt < NKT; ++kt) {
        const int stg = kt & 1;
        if (tid == 0 && kt + 1 < NKT) {
            const u32 sb = sb0 + ((kt+1) & 1) * ASTGB;
            const u32 mb = bar0 + ((kt+1) & 1) * 8;
            MBARRIER_EXPECT_TX(mb, ASTGB);
            TMA_LOAD_2D(sb,        &mK, 0, krow0 + (kt+1)*64, mb);
            TMA_LOAD_2D(sb + KSTG, &mV, 0, krow0 + (kt+1)*64, mb);
        }
        if (tid < 64 && kt + 1 < NKT) Ms[(kt+1) & 1][tid] = mask[b*SEQ + (kt+1)*64 + tid];
        MBARRIER_WAIT_PARITY(bar0 + stg*8, (kt >> 1) & 1);
        const u32 kb = sb0 + stg * ASTGB;

        // ---- S = Q K^T ----
        float S[8][4];
#pragma unroll
        for (int nt = 0; nt < 8; ++nt)
#pragma unroll
            for (int r = 0; r < 4; ++r) S[nt][r] = 0.f;

#pragma unroll
        for (int ks = 0; ks < 4; ++ks) {
            u32 kf[4][4];
#pragma unroll
            for (int g = 0; g < 4; ++g) {
                u32 off = (u32)((g*16 + lrow)*128 + ks*32 + lk16);
                LDSM4(kf[g][0], kf[g][1], kf[g][2], kf[g][3], kb + SW128(off));
            }
#pragma unroll
            for (int nt = 0; nt < 8; ++nt) {
                const int g = nt >> 1, o = nt & 1;
                MMA_F16(S[nt], qf[ks], kf[g][o], kf[g][o+2]);
            }
        }

        // ---- mask ----
        const int c0 = (lane & 3) * 2;
#pragma unroll
        for (int nt = 0; nt < 8; ++nt) {
            if (Ms[stg][nt*8 + c0]     == 0) { S[nt][0] = -1e30f; S[nt][2] = -1e30f; }
            if (Ms[stg][nt*8 + c0 + 1] == 0) { S[nt][1] = -1e30f; S[nt][3] = -1e30f; }
        }

        // ---- online softmax (base-2) ----
        float mx0 = -1e30f, mx1 = -1e30f;
#pragma unroll
        for (int nt = 0; nt < 8; ++nt) {
            mx0 = fmaxf(mx0, fmaxf(S[nt][0], S[nt][1]));
            mx1 = fmaxf(mx1, fmaxf(S[nt][2], S[nt][3]));
        }
#pragma unroll
        for (int off = 1; off < 4; off <<= 1) {
            mx0 = fmaxf(mx0, __shfl_xor_sync(0xffffffffu, mx0, off));
            mx1 = fmaxf(mx1, __shfl_xor_sync(0xffffffffu, mx1, off));
        }
        const float mn0 = fmaxf(m0v, mx0), mn1 = fmaxf(m1v, mx1);
        const float cr0 = exp2_fast(m0v - mn0), cr1 = exp2_fast(m1v - mn1);
        m0v = mn0; m1v = mn1;

        float s0 = 0.f, s1 = 0.f;
        u32 pa[4][4];
#pragma unroll
        for (int t = 0; t < 4; ++t) {
#pragma unroll
            for (int hf = 0; hf < 2; ++hf) {
                const int nt = 2*t + hf;
                float p0 = exp2_fast(S[nt][0] - mn0);
                float p1 = exp2_fast(S[nt][1] - mn0);
                float p2 = exp2_fast(S[nt][2] - mn1);
                float p3 = exp2_fast(S[nt][3] - mn1);
                s0 += p0 + p1; s1 += p2 + p3;
                pa[t][2*hf]     = pack_h16(p0, p1);
                pa[t][2*hf + 1] = pack_h16(p2, p3);
            }
        }
#pragma unroll
        for (int off = 1; off < 4; off <<= 1) {
            s0 += __shfl_xor_sync(0xffffffffu, s0, off);
            s1 += __shfl_xor_sync(0xffffffffu, s1, off);
        }
        l0v = l0v*cr0 + s0;
        l1v = l1v*cr1 + s1;
#pragma unroll
        for (int dt = 0; dt < 8; ++dt) {
            O[dt][0] *= cr0; O[dt][1] *= cr0;
            O[dt][2] *= cr1; O[dt][3] *= cr1;
        }

        // ---- O += P V ----
#pragma unroll
        for (int t = 0; t < 4; ++t) {
            u32 vf[4][4];
#pragma unroll
            for (int dg = 0; dg < 4; ++dg) {
                u32 off = (u32)((t*16 + lrow)*128 + dg*32 + lk16);
                LDSM4T(vf[dg][0], vf[dg][1], vf[dg][2], vf[dg][3], kb + KSTG + SW128(off));
            }
#pragma unroll
            for (int dt = 0; dt < 8; ++dt) {
                const int g = dt >> 1, o = (dt & 1) * 2;
                MMA_F16(O[dt], pa[t], vf[g][o], vf[g][o+1]);
            }
        }
        __syncthreads();
    }

    // ---- epilogue: normalize, write ctx fp16 [m, h*64+d] ----
    const int h = bh & 15;
    const float i0 = 1.f / l0v, i1 = 1.f / l1v;
    const int r = lane >> 2;
    const size_t row0 = (size_t)b*SEQ + q0 + wid*16 + r;
#pragma unroll
    for (int dt = 0; dt < 8; ++dt) {
        const int col = h*HDIM + dt*8 + (lane & 3)*2;
        *(u32*)&g_a[row0*DIMS + col]     = pack_h16(O[dt][0]*i0, O[dt][1]*i0);
        *(u32*)&g_a[(row0+8)*DIMS + col] = pack_h16(O[dt][2]*i1, O[dt][3]*i1);
    }
}

// ---------------- host: tensor map plumbing ----------------
typedef CUresult (*PFN_encode)(CUtensorMap*, CUtensorMapDataType, cuuint32_t, void*,
                               const cuuint64_t*, const cuuint64_t*, const cuuint32_t*,
                               const cuuint32_t*, CUtensorMapInterleave, CUtensorMapSwizzle,
                               CUtensorMapL2promotion, CUtensorMapFloatOOBfill);

static PFN_encode get_encoder() {
    static PFN_encode fn = nullptr;
    if (!fn) {
        cudaDriverEntryPointQueryResult st;
#if CUDART_VERSION >= 12050
        cudaGetDriverEntryPointByVersion("cuTensorMapEncodeTiled", (void**)&fn, 12000,
                                         cudaEnableDefault, &st);
#else
        cudaGetDriverEntryPoint("cuTensorMapEncodeTiled", (void**)&fn, cudaEnableDefault, &st);
#endif
    }
    return fn;
}

static void build_map(PFN_encode enc, CUtensorMap* m, void* ptr,
                      unsigned long long rows, unsigned long long cols,
                      unsigned bx, unsigned by) {
    cuuint64_t dims[2]    = {cols, rows};
    cuuint64_t strides[1] = {cols * 2};
    cuuint32_t box[2]     = {bx, by};
    cuuint32_t es[2]      = {1, 1};
    enc(m, CU_TENSOR_MAP_DATA_TYPE_FLOAT16, 2, ptr, dims, strides, box, es,
        CU_TENSOR_MAP_INTERLEAVE_NONE, CU_TENSOR_MAP_SWIZZLE_128B,
        CU_TENSOR_MAP_L2_PROMOTION_L2_128B, CU_TENSOR_MAP_FLOAT_OOB_FILL_NONE);
}

extern "C" void kernel_launch(void* const* d_in, const int* in_sizes, int n_in,
                              void* d_out, int out_size)
{
    const float* input = (const float*)d_in[0];
    const int*   mask  = (const int*)d_in[1];
    const float* wq = (const float*)d_in[2];
    const float* bq = (const float*)d_in[3];
    const float* wk = (const float*)d_in[4];
    const float* bk = (const float*)d_in[5];
    const float* wv = (const float*)d_in[6];
    const float* bv = (const float*)d_in[7];
    const float* wo = (const float*)d_in[8];
    const float* bo = (const float*)d_in[9];
    float* out = (float*)d_out;
    (void)in_sizes; (void)n_in; (void)out_size;

    PFN_encode enc = get_encoder();
    void *pa, *pw, *pq, *pk, *pv;
    cudaGetSymbolAddress(&pa, g_a);
    cudaGetSymbolAddress(&pw, g_w);
    cudaGetSymbolAddress(&pq, g_q);
    cudaGetSymbolAddress(&pk, g_k);
    cudaGetSymbolAddress(&pv, g_v);

    static CUtensorMap mA, mW, mQ, mK, mV;
    const unsigned long long HR = (unsigned long long)BATCH * NHEAD * SEQ;
    build_map(enc, &mA, pa, MROWS,  DIMS, 64, 256);
    build_map(enc, &mW, pw, 4*DIMS, DIMS, 64, 128);
    build_map(enc, &mQ, pq, HR, HDIM, 64, 128);
    build_map(enc, &mK, pk, HR, HDIM, 64, 64);
    build_map(enc, &mV, pv, HR, HDIM, 64, 64);

    // one fused conversion launch: input + all 4 weights
    const int ncvt = NX4 + 4 * NW4;
    cvt_all<<<(ncvt + 255)/256, 256>>>(input, wq, wk, wv, wo);

    cudaFuncSetAttribute(gemm_kernel<1>, cudaFuncAttributeMaxDynamicSharedMemorySize, GEMM_DSMEM);
    cudaFuncSetAttribute(gemm_kernel<0>, cudaFuncAttributeMaxDynamicSharedMemorySize, GEMM_DSMEM);
    cudaFuncSetAttribute(attn_kernel,    cudaFuncAttributeMaxDynamicSharedMemorySize, ATTN_DSMEM);

    // fused Q/K/V projections (z selects weight + destination)
    gemm_kernel<1><<<dim3(DIMS/128, MROWS/256, 3), 256, GEMM_DSMEM>>>(
        bq, bk, bv, nullptr, mA, mW);

    attn_kernel<<<dim3(SEQ/128, BATCH*NHEAD), 256, ATTN_DSMEM>>>(mask, mQ, mK, mV);

    // output projection (wo), fp32 out
    gemm_kernel<0><<<dim3(DIMS/128, MROWS/256, 1), 256, GEMM_DSMEM>>>(
        bo, nullptr, nullptr, out, mA, mW);
}

// round 10
// speedup vs baseline: 6.9735x; 1.0537x over previous
#include <cuda_runtime.h>
#include <cuda.h>
#include <cuda_fp16.h>
#include <cstdint>

#define BATCH 4
#define SEQ   2048
#define DIMS  1024
#define NHEAD 16
#define HDIM  64
#define MROWS (BATCH*SEQ)

typedef unsigned int u32;
typedef unsigned long long u64;

// ---------------- scratch (static device allocations, TMA-aligned) ----------------
__device__ __align__(1024) __half g_a[(size_t)MROWS*DIMS];    // input / ctx, fp16
__device__ __align__(1024) __half g_w[4ull*DIMS*DIMS];        // wq,wk,wv,wo fp16
__device__ __align__(1024) __half g_q[(size_t)MROWS*DIMS];    // [b,h,s,d]
__device__ __align__(1024) __half g_k[(size_t)MROWS*DIMS];
__device__ __align__(1024) __half g_v[(size_t)MROWS*DIMS];

// ---------------- device helpers ----------------
__device__ __forceinline__ u32 smem_u32(const void* p) {
    u32 a;
    asm("{ .reg .u64 t; cvta.to.shared.u64 t, %1; cvt.u32.u64 %0, t; }" : "=r"(a) : "l"(p));
    return a;
}
#define SW128(o) ((o) ^ (((o) >> 3) & 0x70))

#define MBARRIER_INIT(mb, cnt) \
    asm volatile("mbarrier.init.shared.b64 [%0], %1;" :: "r"((u32)(mb)), "r"((u32)(cnt)) : "memory")
#define MBARRIER_EXPECT_TX(mb, bytes) \
    asm volatile("mbarrier.arrive.expect_tx.shared.b64 _, [%0], %1;" \
                 :: "r"((u32)(mb)), "r"((u32)(bytes)) : "memory")
#define MBARRIER_WAIT_PARITY(mb, par) do { \
    u32 _m = (u32)(mb); u32 _p = (u32)(par); u32 _done; \
    asm volatile("{\n\t.reg .pred p;\n\t" \
        "mbarrier.try_wait.parity.acquire.cta.shared::cta.b64 p, [%1], %2;\n\t" \
        "selp.b32 %0, 1, 0, p;\n\t}" : "=r"(_done) : "r"(_m), "r"(_p) : "memory"); \
    if (!_done) { \
        asm volatile("{\n\t.reg .pred P1;\n\t" \
            "WL_%=:\n\t" \
            "mbarrier.try_wait.parity.acquire.cta.shared::cta.b64 P1, [%0], %1, 0x989680;\n\t" \
            "@P1 bra.uni WD_%=;\n\t" \
            "bra.uni WL_%=;\n\t" \
            "WD_%=:\n\t}" :: "r"(_m), "r"(_p) : "memory"); \
    } } while (0)

#define TMA_LOAD_2D(dst, map, x, y, mbar) \
    asm volatile("cp.async.bulk.tensor.2d.shared::cta.global.tile.mbarrier::complete_tx::bytes " \
                 "[%0], [%1, {%2, %3}], [%4];" \
                 :: "r"((u32)(dst)), "l"(map), "r"((int)(x)), "r"((int)(y)), "r"((u32)(mbar)) \
                 : "memory")

#define LDSM4(r0, r1, r2, r3, a) \
    asm volatile("ldmatrix.sync.aligned.m8n8.x4.shared.b16 {%0,%1,%2,%3}, [%4];" \
                 : "=r"(r0), "=r"(r1), "=r"(r2), "=r"(r3) : "r"(a))
#define LDSM4T(r0, r1, r2, r3, a) \
    asm volatile("ldmatrix.sync.aligned.m8n8.x4.trans.shared.b16 {%0,%1,%2,%3}, [%4];" \
                 : "=r"(r0), "=r"(r1), "=r"(r2), "=r"(r3) : "r"(a))
#define MMA_F16(d, a, b0, b1) \
    asm volatile("mma.sync.aligned.m16n8k16.row.col.f32.f16.f16.f32 " \
                 "{%0,%1,%2,%3}, {%4,%5,%6,%7}, {%8,%9}, {%0,%1,%2,%3};" \
                 : "+f"((d)[0]), "+f"((d)[1]), "+f"((d)[2]), "+f"((d)[3]) \
                 : "r"((a)[0]), "r"((a)[1]), "r"((a)[2]), "r"((a)[3]), \
                   "r"(b0), "r"(b1))

__device__ __forceinline__ u32 pack_h16(float a, float b) {
    __half2 t = __floats2half2_rn(a, b);
    return *(u32*)&t;
}
__device__ __forceinline__ float exp2_fast(float t) {
    t = fmaxf(t, -126.0f);
    float r = t + 12582912.0f;
    int   i = __float_as_int(r) << 23;
    float f = t - (r - 12582912.0f);
    float p = fmaf(f, 0.00961813f, 0.05550411f);
    p = fmaf(f, p, 0.24022651f);
    p = fmaf(f, p, 0.69314718f);
    p = fmaf(f, p, 1.0f);
    return __int_as_float(__float_as_int(p) + i);
}

// ---------------- fused conversion: input + 4 weights in one launch ----------------
#define NX4 (MROWS*DIMS/4)
#define NW4 (DIMS*DIMS/4)
__global__ void cvt_all(const float* __restrict__ input,
                        const float* __restrict__ wq, const float* __restrict__ wk,
                        const float* __restrict__ wv, const float* __restrict__ wo)
{
    int i = blockIdx.x * 256 + threadIdx.x;
    const float* src;
    u32* dst;
    if (i < NX4) {
        src = input; dst = (u32*)g_a;
    } else {
        int j = i - NX4;
        int seg = j / NW4;
        i = j - seg * NW4;
        src = (seg == 0) ? wq : (seg == 1) ? wk : (seg == 2) ? wv : wo;
        dst = (u32*)(g_w + (size_t)seg * DIMS * DIMS);
    }
    float4 v = ((const float4*)src)[i];
    dst[i*2+0] = pack_h16(v.x, v.y);
    dst[i*2+1] = pack_h16(v.z, v.w);
}

// ---------------- TMA fp16 GEMM, 128x128 tile, 2 CTAs/SM ----------------
// C[m0:+128, n0:+128] = scale*(A @ W^T + bias)
// FUSED=1: blockIdx.z in {0,1,2} selects wq/wk/wv and g_q/g_k/g_v output.
// FUSED=0: wo, fp32 output.
#define ASTG   16384                 // 128 x 128B
#define BSTG   16384                 // 128 x 128B
#define STAGEB (ASTG + BSTG)         // 32768
#define GEMM_DSMEM (2*STAGEB + 1024)

template<int FUSED>
__global__ __launch_bounds__(256, 2) void gemm_kernel(
    const float* __restrict__ bq, const float* __restrict__ bk,
    const float* __restrict__ bv, float* __restrict__ outp,
    const __grid_constant__ CUtensorMap mA,
    const __grid_constant__ CUtensorMap mW)
{
    extern __shared__ char dyn[];
    __shared__ float s_bias[128];
    __shared__ __align__(8) u64 s_bar[2];

    const int tid = threadIdx.x, wid = tid >> 5, lane = tid & 31;
    const int z = FUSED ? blockIdx.z : 3;
    const int m0 = blockIdx.y * 128, n0 = blockIdx.x * 128;
    const int wrow = z * DIMS + n0;
    const int wm = (wid >> 2) * 64, wn = (wid & 3) * 32;   // warp grid 2(m) x 4(n)
    const u32 sb0 = (smem_u32(dyn) + 1023u) & ~1023u;
    const u32 bar0 = smem_u32(&s_bar[0]);
    const float scale = (FUSED && z == 0) ? 0.125f * 1.44269504f : 1.0f;

    if (tid < 128) {
        const float* bp = FUSED ? (z == 0 ? bq : z == 1 ? bk : bv) : bq;
        s_bias[tid] = bp[n0 + tid];
    }
    if (tid == 0) { MBARRIER_INIT(bar0, 1); MBARRIER_INIT(bar0 + 8, 1); }
    __syncthreads();

    if (tid == 0) {
        MBARRIER_EXPECT_TX(bar0, STAGEB);
        TMA_LOAD_2D(sb0,        &mA, 0, m0,   bar0);
        TMA_LOAD_2D(sb0 + ASTG, &mW, 0, wrow, bar0);
    }

    float acc[4][4][4];
#pragma unroll
    for (int i = 0; i < 4; ++i)
#pragma unroll
        for (int j = 0; j < 4; ++j)
#pragma unroll
            for (int r = 0; r < 4; ++r) acc[i][j][r] = 0.f;

    const int lrow = lane & 15;
    const int lk16 = ((lane >> 4) & 1) * 16;

    for (int it = 0; it < 16; ++it) {
        if (tid == 0 && it + 1 < 16) {
            const u32 sb = sb0 + ((it+1) & 1) * STAGEB;
            const u32 mb = bar0 + ((it+1) & 1) * 8;
            MBARRIER_EXPECT_TX(mb, STAGEB);
            TMA_LOAD_2D(sb,        &mA, (it+1)*64, m0,   mb);
            TMA_LOAD_2D(sb + ASTG, &mW, (it+1)*64, wrow, mb);
        }
        MBARRIER_WAIT_PARITY(bar0 + (it & 1)*8, (it >> 1) & 1);
        const u32 st = sb0 + (it & 1) * STAGEB;

#pragma unroll
        for (int ks = 0; ks < 4; ++ks) {
            u32 a[4][4], bw[2][4];
#pragma unroll
            for (int ti = 0; ti < 4; ++ti) {
                u32 off = (u32)((wm + ti*16 + lrow)*128 + ks*32 + lk16);
                LDSM4(a[ti][0], a[ti][1], a[ti][2], a[ti][3], st + SW128(off));
            }
#pragma unroll
            for (int g = 0; g < 2; ++g) {
                u32 off = (u32)((wn + g*16 + lrow)*128 + ks*32 + lk16);
                LDSM4(bw[g][0], bw[g][1], bw[g][2], bw[g][3], st + ASTG + SW128(off));
            }
#pragma unroll
            for (int ti = 0; ti < 4; ++ti) {
#pragma unroll
                for (int nj = 0; nj < 4; ++nj) {
                    const int g = nj >> 1, o = nj & 1;
                    MMA_F16(acc[ti][nj], a[ti], bw[g][o], bw[g][o+2]);
                }
            }
        }
        __syncthreads();
    }

#pragma unroll
    for (int ti = 0; ti < 4; ++ti) {
#pragma unroll
        for (int nj = 0; nj < 4; ++nj) {
            const int col = wn + nj*8 + (lane & 3)*2;
            const int r0  = m0 + wm + ti*16 + (lane >> 2);
            const float b0 = s_bias[col], b1 = s_bias[col + 1];
            float v0 = (acc[ti][nj][0] + b0) * scale;
            float v1 = (acc[ti][nj][1] + b1) * scale;
            float v2 = (acc[ti][nj][2] + b0) * scale;
            float v3 = (acc[ti][nj][3] + b1) * scale;
            if (FUSED) {
                __half* dst = (z == 0) ? g_q : (z == 1) ? g_k : g_v;
                const int nglob = n0 + col;
                const int hh = nglob >> 6, dd = nglob & 63;
                const int bb = r0 >> 11, ss = r0 & 2047;
                const size_t base = (((size_t)bb*NHEAD + hh)*SEQ + ss)*HDIM + dd;
                *(u32*)&dst[base]          = pack_h16(v0, v1);
                *(u32*)&dst[base + 8*HDIM] = pack_h16(v2, v3);
            } else {
                *(float2*)&outp[(size_t)r0 * DIMS + n0 + col]     = make_float2(v0, v1);
                *(float2*)&outp[(size_t)(r0+8) * DIMS + n0 + col] = make_float2(v2, v3);
            }
        }
    }
}

// ---------------- TMA flash attention (single fp16, 2 CTAs/SM) ----------------
#define NKT   (SEQ/64)
#define KSTG  8192                  // 64 x 128B
#define ASTGB (2*KSTG)              // K, V
#define QB    16384                 // 128 x 128B
#define ATTN_DSMEM (2*ASTGB + QB + 1024)

__global__ __launch_bounds__(256, 2) void attn_kernel(
    const int* __restrict__ mask,
    const __grid_constant__ CUtensorMap mQ,
    const __grid_constant__ CUtensorMap mK,
    const __grid_constant__ CUtensorMap mV)
{
    extern __shared__ char dyn[];
    __shared__ int Ms[2][64];
    __shared__ __align__(8) u64 s_bar[3];

    const int tid = threadIdx.x, wid = tid >> 5, lane = tid & 31;
    const int bh = blockIdx.y, b = bh >> 4;
    const int q0 = blockIdx.x * 128;
    const int krow0 = bh * SEQ;
    const u32 sb0 = (smem_u32(dyn) + 1023u) & ~1023u;
    const u32 qb  = sb0 + 2*ASTGB;
    const u32 bar0 = smem_u32(&s_bar[0]);

    if (tid == 0) {
        MBARRIER_INIT(bar0, 1); MBARRIER_INIT(bar0 + 8, 1); MBARRIER_INIT(bar0 + 16, 1);
    }
    __syncthreads();

    if (tid == 0) {
        MBARRIER_EXPECT_TX(bar0 + 16, QB);
        TMA_LOAD_2D(qb, &mQ, 0, krow0 + q0, bar0 + 16);
        MBARRIER_EXPECT_TX(bar0, ASTGB);
        TMA_LOAD_2D(sb0,        &mK, 0, krow0, bar0);
        TMA_LOAD_2D(sb0 + KSTG, &mV, 0, krow0, bar0);
    }
    if (tid < 64) Ms[0][tid] = mask[b*SEQ + tid];

    const int lrow = lane & 15;
    const int lk16 = ((lane >> 4) & 1) * 16;

    MBARRIER_WAIT_PARITY(bar0 + 16, 0);
    u32 qf[4][4];
#pragma unroll
    for (int ks = 0; ks < 4; ++ks) {
        u32 off = (u32)((wid*16 + lrow)*128 + ks*32 + lk16);
        LDSM4(qf[ks][0], qf[ks][1], qf[ks][2], qf[ks][3], qb + SW128(off));
    }
    __syncthreads();

    float O[8][4];
#pragma unroll
    for (int dt = 0; dt < 8; ++dt)
#pragma unroll
        for (int r = 0; r < 4; ++r) O[dt][r] = 0.f;
    float m0v = -1e30f, m1v = -1e30f, l0v = 0.f, l1v = 0.f;

    for (int kt = 0; kt < NKT; ++kt) {
        const int stg = kt & 1;
        if (tid == 0 && kt + 1 < NKT) {
            const u32 sb = sb0 + ((kt+1) & 1) * ASTGB;
            const u32 mb = bar0 + ((kt+1) & 1) * 8;
            MBARRIER_EXPECT_TX(mb, ASTGB);
            TMA_LOAD_2D(sb,        &mK, 0, krow0 + (kt+1)*64, mb);
            TMA_LOAD_2D(sb + KSTG, &mV, 0, krow0 + (kt+1)*64, mb);
        }
        if (tid < 64 && kt + 1 < NKT) Ms[(kt+1) & 1][tid] = mask[b*SEQ + (kt+1)*64 + tid];
        MBARRIER_WAIT_PARITY(bar0 + stg*8, (kt >> 1) & 1);
        const u32 kb = sb0 + stg * ASTGB;

        // ---- S = Q K^T ----
        float S[8][4];
#pragma unroll
        for (int nt = 0; nt < 8; ++nt)
#pragma unroll
            for (int r = 0; r < 4; ++r) S[nt][r] = 0.f;

#pragma unroll
        for (int ks = 0; ks < 4; ++ks) {
            u32 kf[4][4];
#pragma unroll
            for (int g = 0; g < 4; ++g) {
                u32 off = (u32)((g*16 + lrow)*128 + ks*32 + lk16);
                LDSM4(kf[g][0], kf[g][1], kf[g][2], kf[g][3], kb + SW128(off));
            }
#pragma unroll
            for (int nt = 0; nt < 8; ++nt) {
                const int g = nt >> 1, o = nt & 1;
                MMA_F16(S[nt], qf[ks], kf[g][o], kf[g][o+2]);
            }
        }

        // ---- mask ----
        const int c0 = (lane & 3) * 2;
#pragma unroll
        for (int nt = 0; nt < 8; ++nt) {
            if (Ms[stg][nt*8 + c0]     == 0) { S[nt][0] = -1e30f; S[nt][2] = -1e30f; }
            if (Ms[stg][nt*8 + c0 + 1] == 0) { S[nt][1] = -1e30f; S[nt][3] = -1e30f; }
        }

        // ---- online softmax (base-2) ----
        float mx0 = -1e30f, mx1 = -1e30f;
#pragma unroll
        for (int nt = 0; nt < 8; ++nt) {
            mx0 = fmaxf(mx0, fmaxf(S[nt][0], S[nt][1]));
            mx1 = fmaxf(mx1, fmaxf(S[nt][2], S[nt][3]));
        }
#pragma unroll
        for (int off = 1; off < 4; off <<= 1) {
            mx0 = fmaxf(mx0, __shfl_xor_sync(0xffffffffu, mx0, off));
            mx1 = fmaxf(mx1, __shfl_xor_sync(0xffffffffu, mx1, off));
        }
        const float mn0 = fmaxf(m0v, mx0), mn1 = fmaxf(m1v, mx1);
        const float cr0 = exp2_fast(m0v - mn0), cr1 = exp2_fast(m1v - mn1);
        m0v = mn0; m1v = mn1;

        float s0 = 0.f, s1 = 0.f;
        u32 pa[4][4];
#pragma unroll
        for (int t = 0; t < 4; ++t) {
#pragma unroll
            for (int hf = 0; hf < 2; ++hf) {
                const int nt = 2*t + hf;
                float p0 = exp2_fast(S[nt][0] - mn0);
                float p1 = exp2_fast(S[nt][1] - mn0);
                float p2 = exp2_fast(S[nt][2] - mn1);
                float p3 = exp2_fast(S[nt][3] - mn1);
                s0 += p0 + p1; s1 += p2 + p3;
                pa[t][2*hf]     = pack_h16(p0, p1);
                pa[t][2*hf + 1] = pack_h16(p2, p3);
            }
        }
#pragma unroll
        for (int off = 1; off < 4; off <<= 1) {
            s0 += __shfl_xor_sync(0xffffffffu, s0, off);
            s1 += __shfl_xor_sync(0xffffffffu, s1, off);
        }
        l0v = l0v*cr0 + s0;
        l1v = l1v*cr1 + s1;
#pragma unroll
        for (int dt = 0; dt < 8; ++dt) {
            O[dt][0] *= cr0; O[dt][1] *= cr0;
            O[dt][2] *= cr1; O[dt][3] *= cr1;
        }

        // ---- O += P V ----
#pragma unroll
        for (int t = 0; t < 4; ++t) {
            u32 vf[4][4];
#pragma unroll
            for (int dg = 0; dg < 4; ++dg) {
                u32 off = (u32)((t*16 + lrow)*128 + dg*32 + lk16);
                LDSM4T(vf[dg][0], vf[dg][1], vf[dg][2], vf[dg][3], kb + KSTG + SW128(off));
            }
#pragma unroll
            for (int dt = 0; dt < 8; ++dt) {
                const int g = dt >> 1, o = (dt & 1) * 2;
                MMA_F16(O[dt], pa[t], vf[g][o], vf[g][o+1]);
            }
        }
        __syncthreads();
    }

    // ---- epilogue: normalize, write ctx fp16 [m, h*64+d] ----
    const int h = bh & 15;
    const float i0 = 1.f / l0v, i1 = 1.f / l1v;
    const int r = lane >> 2;
    const size_t row0 = (size_t)b*SEQ + q0 + wid*16 + r;
#pragma unroll
    for (int dt = 0; dt < 8; ++dt) {
        const int col = h*HDIM + dt*8 + (lane & 3)*2;
        *(u32*)&g_a[row0*DIMS + col]     = pack_h16(O[dt][0]*i0, O[dt][1]*i0);
        *(u32*)&g_a[(row0+8)*DIMS + col] = pack_h16(O[dt][2]*i1, O[dt][3]*i1);
    }
}

// ---------------- host: tensor map plumbing ----------------
typedef CUresult (*PFN_encode)(CUtensorMap*, CUtensorMapDataType, cuuint32_t, void*,
                               const cuuint64_t*, const cuuint64_t*, const cuuint32_t*,
                               const cuuint32_t*, CUtensorMapInterleave, CUtensorMapSwizzle,
                               CUtensorMapL2promotion, CUtensorMapFloatOOBfill);

static PFN_encode get_encoder() {
    static PFN_encode fn = nullptr;
    if (!fn) {
        cudaDriverEntryPointQueryResult st;
#if CUDART_VERSION >= 12050
        cudaGetDriverEntryPointByVersion("cuTensorMapEncodeTiled", (void**)&fn, 12000,
                                         cudaEnableDefault, &st);
#else
        cudaGetDriverEntryPoint("cuTensorMapEncodeTiled", (void**)&fn, cudaEnableDefault, &st);
#endif
    }
    return fn;
}

static void build_map(PFN_encode enc, CUtensorMap* m, void* ptr,
                      unsigned long long rows, unsigned long long cols,
                      unsigned bx, unsigned by) {
    cuuint64_t dims[2]    = {cols, rows};
    cuuint64_t strides[1] = {cols * 2};
    cuuint32_t box[2]     = {bx, by};
    cuuint32_t es[2]      = {1, 1};
    enc(m, CU_TENSOR_MAP_DATA_TYPE_FLOAT16, 2, ptr, dims, strides, box, es,
        CU_TENSOR_MAP_INTERLEAVE_NONE, CU_TENSOR_MAP_SWIZZLE_128B,
        CU_TENSOR_MAP_L2_PROMOTION_L2_128B, CU_TENSOR_MAP_FLOAT_OOB_FILL_NONE);
}

extern "C" void kernel_launch(void* const* d_in, const int* in_sizes, int n_in,
                              void* d_out, int out_size)
{
    const float* input = (const float*)d_in[0];
    const int*   mask  = (const int*)d_in[1];
    const float* wq = (const float*)d_in[2];
    const float* bq = (const float*)d_in[3];
    const float* wk = (const float*)d_in[4];
    const float* bk = (const float*)d_in[5];
    const float* wv = (const float*)d_in[6];
    const float* bv = (const float*)d_in[7];
    const float* wo = (const float*)d_in[8];
    const float* bo = (const float*)d_in[9];
    float* out = (float*)d_out;
    (void)in_sizes; (void)n_in; (void)out_size;

    PFN_encode enc = get_encoder();
    void *pa, *pw, *pq, *pk, *pv;
    cudaGetSymbolAddress(&pa, g_a);
    cudaGetSymbolAddress(&pw, g_w);
    cudaGetSymbolAddress(&pq, g_q);
    cudaGetSymbolAddress(&pk, g_k);
    cudaGetSymbolAddress(&pv, g_v);

    static CUtensorMap mA, mW, mQ, mK, mV;
    const unsigned long long HR = (unsigned long long)BATCH * NHEAD * SEQ;
    build_map(enc, &mA, pa, MROWS,  DIMS, 64, 128);
    build_map(enc, &mW, pw, 4*DIMS, DIMS, 64, 128);
    build_map(enc, &mQ, pq, HR, HDIM, 64, 128);
    build_map(enc, &mK, pk, HR, HDIM, 64, 64);
    build_map(enc, &mV, pv, HR, HDIM, 64, 64);

    // one fused conversion launch: input + all 4 weights
    const int ncvt = NX4 + 4 * NW4;
    cvt_all<<<(ncvt + 255)/256, 256>>>(input, wq, wk, wv, wo);

    cudaFuncSetAttribute(gemm_kernel<1>, cudaFuncAttributeMaxDynamicSharedMemorySize, GEMM_DSMEM);
    cudaFuncSetAttribute(gemm_kernel<0>, cudaFuncAttributeMaxDynamicSharedMemorySize, GEMM_DSMEM);
    cudaFuncSetAttribute(attn_kernel,    cudaFuncAttributeMaxDynamicSharedMemorySize, ATTN_DSMEM);

    // fused Q/K/V projections (z selects weight + destination)
    gemm_kernel<1><<<dim3(DIMS/128, MROWS/128, 3), 256, GEMM_DSMEM>>>(
        bq, bk, bv, nullptr, mA, mW);

    attn_kernel<<<dim3(SEQ/128, BATCH*NHEAD), 256, ATTN_DSMEM>>>(mask, mQ, mK, mV);

    // output projection (wo), fp32 out
    gemm_kernel<0><<<dim3(DIMS/128, MROWS/128, 1), 256, GEMM_DSMEM>>>(
        bo, nullptr, nullptr, out, mA, mW);
}